// round 1
// baseline (speedup 1.0000x reference)
#include <cuda_runtime.h>
#include <math.h>

#define BN_EPS 1e-5f
#define BATCH 8192

// ---------------- scratch (device globals; no allocations allowed) ----------
__device__ float g_h[(size_t)BATCH * 32 * 16 * 16];   // conv1 output (268MB)
__device__ float g_f[(size_t)BATCH * 64 * 8 * 8];     // flattened feat (134MB)
__device__ float g_h1[(size_t)BATCH * 512];           // fc1 output (16MB)

// ============================================================================
// Kernel 1: conv1 (3->32, 5x5, stride2, pad2) + BN + ReLU.  One block/image.
// ============================================================================
__global__ __launch_bounds__(256) void conv1_kernel(
    const float* __restrict__ x, const float* __restrict__ w1,
    const float* __restrict__ b1, const float* __restrict__ g1,
    const float* __restrict__ be1, const float* __restrict__ m1,
    const float* __restrict__ v1)
{
    __shared__ float xs[3 * 32 * 32];        // 12KB input
    __shared__ float ws[3 * 25 * 32];        // weights transposed [ic*25+k][c], 9.6KB
    __shared__ float sc[32], bi[32];

    const int n = blockIdx.x;
    const int t = threadIdx.x;

    const float* xg = x + (size_t)n * 3072;
    for (int i = t; i < 3072; i += 256) xs[i] = xg[i];

    // w1 layout (32,3,5,5) -> ws[(ic*25+ky*5+kx)*32 + c]
    for (int i = t; i < 2400; i += 256) {
        int c = i / 75, r = i % 75;
        ws[r * 32 + c] = w1[i];
    }
    if (t < 32) {
        float s = g1[t] * rsqrtf(v1[t] + BN_EPS);
        sc[t] = s;
        bi[t] = be1[t] + (b1[t] - m1[t]) * s;
    }
    __syncthreads();

    const int oy = t >> 4, ox = t & 15;   // each thread: one output position, all 32 ch
    float acc[32];
#pragma unroll
    for (int c = 0; c < 32; c++) acc[c] = 0.f;

    for (int ky = 0; ky < 5; ky++) {
        int iy = oy * 2 - 2 + ky;
        if (iy < 0 || iy > 31) continue;
        for (int kx = 0; kx < 5; kx++) {
            int ix = ox * 2 - 2 + kx;
            if (ix < 0 || ix > 31) continue;
            float v0 = xs[          iy * 32 + ix];
            float va = xs[1024 +    iy * 32 + ix];
            float vb = xs[2048 +    iy * 32 + ix];
            const float* w0 = &ws[(      ky * 5 + kx) * 32];
            const float* w1p = &ws[(25  + ky * 5 + kx) * 32];
            const float* w2p = &ws[(50  + ky * 5 + kx) * 32];
#pragma unroll
            for (int c4 = 0; c4 < 8; c4++) {
                float4 wA = *(const float4*)(w0  + c4 * 4);
                float4 wB = *(const float4*)(w1p + c4 * 4);
                float4 wC = *(const float4*)(w2p + c4 * 4);
                acc[c4 * 4 + 0] += v0 * wA.x + va * wB.x + vb * wC.x;
                acc[c4 * 4 + 1] += v0 * wA.y + va * wB.y + vb * wC.y;
                acc[c4 * 4 + 2] += v0 * wA.z + va * wB.z + vb * wC.z;
                acc[c4 * 4 + 3] += v0 * wA.w + va * wB.w + vb * wC.w;
            }
        }
    }

    float* hg = g_h + (size_t)n * 8192;
#pragma unroll
    for (int c = 0; c < 32; c++) {
        float y = acc[c] * sc[c] + bi[c];
        hg[c * 256 + t] = fmaxf(y, 0.f);
    }
}

// ============================================================================
// Kernel 2: conv2 (32->64, 3x3, s2, p1) + BN + ReLU + Haar cD * upsample
//           + 1x1 attn sigmoid + multiply  ->  g_f  (flattened, NCHW order)
// Persistent blocks: weights loaded into smem ONCE per block.
// Dynamic smem layout (floats):
//   hin : 32*18*18 = 10368   (zero-padded input)
//   ws  : 32*9*64  = 18432   (transposed [ic*9+q][c])
//   feat: 64*64    = 4096
//   attn: 64, sc2: 64, bi2: 64, was: 64     total 33152 floats = 132,608 B
// ============================================================================
__global__ __launch_bounds__(512) void conv2_fused_kernel(
    const float* __restrict__ w2, const float* __restrict__ b2,
    const float* __restrict__ g2, const float* __restrict__ be2,
    const float* __restrict__ m2, const float* __restrict__ v2,
    const float* __restrict__ wa, const float* __restrict__ ba)
{
    extern __shared__ float sm[];
    float* hin  = sm;                // 10368
    float* ws   = sm + 10368;        // 18432
    float* feat = sm + 28800;        // 4096
    float* attn = sm + 32896;        // 64
    float* sc2  = sm + 32960;        // 64
    float* bi2  = sm + 33024;        // 64
    float* was  = sm + 33088;        // 64

    const int t = threadIdx.x;   // 512 threads

    // w2 (64,32,3,3) -> ws[(ic*9+q)*64 + c]
    for (int i = t; i < 18432; i += 512) {
        int c = i / 288, r = i % 288;
        ws[r * 64 + c] = w2[i];
    }
    if (t < 64) {
        float s = g2[t] * rsqrtf(v2[t] + BN_EPS);
        sc2[t] = s;
        bi2[t] = be2[t] + (b2[t] - m2[t]) * s;
        was[t] = wa[t];
    }
    for (int i = t; i < 10368; i += 512) hin[i] = 0.f;  // padding stays 0 forever
    const float bav = ba[0];
    __syncthreads();

    // thread tiling: 4 channels x 2 positions
    const int ct  = t >> 5;            // 0..15 -> channels ct*4..+3
    const int pt  = t & 31;            // 0..31
    const int c0  = ct * 4;
    const int oh  = pt >> 2;           // 0..7
    const int ow0 = (pt & 3) * 2;      // 0,2,4,6

    for (int n = blockIdx.x; n < BATCH; n += gridDim.x) {
        const float* hg = g_h + (size_t)n * 8192;
        for (int i = t; i < 8192; i += 512) {
            int ic = i >> 8, p = i & 255, y = p >> 4, xx = p & 15;
            hin[ic * 324 + (y + 1) * 18 + (xx + 1)] = hg[i];
        }
        __syncthreads();

        float acc00=0.f, acc01=0.f, acc10=0.f, acc11=0.f,
              acc20=0.f, acc21=0.f, acc30=0.f, acc31=0.f;

        for (int ic = 0; ic < 32; ic++) {
            const float* hi = hin + ic * 324;
            const float* wrow = ws + ic * 9 * 64 + c0;
#pragma unroll
            for (int kh = 0; kh < 3; kh++) {
                const float* hr = hi + (oh * 2 + kh) * 18 + ow0 * 2;
#pragma unroll
                for (int kw = 0; kw < 3; kw++) {
                    float4 w4 = *(const float4*)(wrow + (kh * 3 + kw) * 64);
                    float i0 = hr[kw];
                    float i1 = hr[kw + 2];
                    acc00 += w4.x * i0;  acc01 += w4.x * i1;
                    acc10 += w4.y * i0;  acc11 += w4.y * i1;
                    acc20 += w4.z * i0;  acc21 += w4.z * i1;
                    acc30 += w4.w * i0;  acc31 += w4.w * i1;
                }
            }
        }

        // BN + ReLU -> feat
        {
            int p = oh * 8 + ow0;
            float s0 = sc2[c0+0], s1 = sc2[c0+1], s2 = sc2[c0+2], s3 = sc2[c0+3];
            float t0 = bi2[c0+0], t1 = bi2[c0+1], t2 = bi2[c0+2], t3 = bi2[c0+3];
            feat[(c0+0)*64 + p    ] = fmaxf(acc00*s0 + t0, 0.f);
            feat[(c0+0)*64 + p + 1] = fmaxf(acc01*s0 + t0, 0.f);
            feat[(c0+1)*64 + p    ] = fmaxf(acc10*s1 + t1, 0.f);
            feat[(c0+1)*64 + p + 1] = fmaxf(acc11*s1 + t1, 0.f);
            feat[(c0+2)*64 + p    ] = fmaxf(acc20*s2 + t2, 0.f);
            feat[(c0+2)*64 + p + 1] = fmaxf(acc21*s2 + t2, 0.f);
            feat[(c0+3)*64 + p    ] = fmaxf(acc30*s3 + t3, 0.f);
            feat[(c0+3)*64 + p + 1] = fmaxf(acc31*s3 + t3, 0.f);
        }
        __syncthreads();

        // Haar cD per channel per 2x2 block, multiplied back (upsampled)
        for (int q = t; q < 1024; q += 512) {
            int c = q >> 4, blk = q & 15;
            int bI = blk >> 2, bJ = blk & 3;
            int p00 = c * 64 + (bI * 2) * 8 + bJ * 2;
            float a = feat[p00], b = feat[p00 + 1];
            float cc = feat[p00 + 8], d = feat[p00 + 9];
            float v = (a - b - cc + d) * 0.5f;
            feat[p00]     = a  * v;
            feat[p00 + 1] = b  * v;
            feat[p00 + 8] = cc * v;
            feat[p00 + 9] = d  * v;
        }
        __syncthreads();

        // 1x1 attention conv over channels -> sigmoid
        if (t < 64) {
            float s = bav;
            for (int c = 0; c < 64; c++) s += feat[c * 64 + t] * was[c];
            attn[t] = 1.f / (1.f + __expf(-s));
        }
        __syncthreads();

        // multiply & write flattened feature
        float* fg = g_f + (size_t)n * 4096;
        for (int i = t; i < 4096; i += 512) {
            fg[i] = feat[i] * attn[i & 63];
        }
        __syncthreads();   // feat/hin reused next image
    }
}

// ============================================================================
// Kernel 3: fc1  h1 = relu(f @ wd1^T + bd1)
// SGEMM 128x64x8 tile, 256 threads, 8x4 per thread.  M=8192 N=512 K=4096.
// ============================================================================
__global__ __launch_bounds__(256) void fc1_kernel(
    const float* __restrict__ wd1, const float* __restrict__ bd1)
{
    __shared__ float As[8][128];
    __shared__ float Bs[8][64];

    const int t  = threadIdx.x;
    const int tx = t & 15;       // N dir: 16*4 = 64
    const int ty = t >> 4;       // M dir: 16*8 = 128
    const int bm = blockIdx.x;   // 64
    const int bn = blockIdx.y;   // 8

    const float* Ab = g_f + (size_t)(bm * 128) * 4096;
    const float* Bb = wd1 + (size_t)(bn * 64) * 4096;

    const int arow = t >> 1;         // 0..127
    const int acol = (t & 1) * 4;    // 0 or 4
    const int brow = t >> 1;         // 0..63 (only t<128)
    const int bcol = (t & 1) * 4;

    float acc[8][4];
#pragma unroll
    for (int i = 0; i < 8; i++)
#pragma unroll
        for (int j = 0; j < 4; j++) acc[i][j] = 0.f;

    for (int k0 = 0; k0 < 4096; k0 += 8) {
        float4 av = *(const float4*)&Ab[(size_t)arow * 4096 + k0 + acol];
        float4 bv = make_float4(0.f, 0.f, 0.f, 0.f);
        if (t < 128)
            bv = *(const float4*)&Bb[(size_t)brow * 4096 + k0 + bcol];
        __syncthreads();
        As[acol + 0][arow] = av.x;
        As[acol + 1][arow] = av.y;
        As[acol + 2][arow] = av.z;
        As[acol + 3][arow] = av.w;
        if (t < 128) {
            Bs[bcol + 0][brow] = bv.x;
            Bs[bcol + 1][brow] = bv.y;
            Bs[bcol + 2][brow] = bv.z;
            Bs[bcol + 3][brow] = bv.w;
        }
        __syncthreads();
#pragma unroll
        for (int k = 0; k < 8; k++) {
            float4 a0 = *(const float4*)&As[k][ty * 8];
            float4 a1 = *(const float4*)&As[k][ty * 8 + 4];
            float4 b  = *(const float4*)&Bs[k][tx * 4];
            float am[8] = {a0.x, a0.y, a0.z, a0.w, a1.x, a1.y, a1.z, a1.w};
            float bn4[4] = {b.x, b.y, b.z, b.w};
#pragma unroll
            for (int i = 0; i < 8; i++)
#pragma unroll
                for (int j = 0; j < 4; j++)
                    acc[i][j] += am[i] * bn4[j];
        }
    }

    const int m0 = bm * 128 + ty * 8;
    const int n0 = bn * 64 + tx * 4;
    float bias[4] = {bd1[n0], bd1[n0+1], bd1[n0+2], bd1[n0+3]};
#pragma unroll
    for (int i = 0; i < 8; i++) {
        float* row = g_h1 + (size_t)(m0 + i) * 512 + n0;
#pragma unroll
        for (int j = 0; j < 4; j++)
            row[j] = fmaxf(acc[i][j] + bias[j], 0.f);
    }
}

// ============================================================================
// Kernel 4: fc2  out = sigmoid(h1 @ wd2^T + bd2).  16 rows per block.
// ============================================================================
__global__ __launch_bounds__(128) void fc2_kernel(
    const float* __restrict__ wd2, const float* __restrict__ bd2,
    float* __restrict__ out)
{
    __shared__ float sh[16 * 512];
    const int mb = blockIdx.x * 16;
    const int t = threadIdx.x;  // 128 = one output column each

    const float4* src = (const float4*)(g_h1 + (size_t)mb * 512);
    for (int i = t; i < 16 * 512 / 4; i += 128)
        ((float4*)sh)[i] = src[i];
    __syncthreads();

    float acc[16];
#pragma unroll
    for (int i = 0; i < 16; i++) acc[i] = 0.f;

    const float* wr = wd2 + (size_t)t * 512;
#pragma unroll 2
    for (int k = 0; k < 512; k += 4) {
        float4 w = *(const float4*)&wr[k];
#pragma unroll
        for (int mi = 0; mi < 16; mi++) {
            float4 hv = *(const float4*)&sh[mi * 512 + k];
            acc[mi] += hv.x * w.x + hv.y * w.y + hv.z * w.z + hv.w * w.w;
        }
    }

    const float b = bd2[t];
#pragma unroll
    for (int mi = 0; mi < 16; mi++) {
        float s = acc[mi] + b;
        out[(size_t)(mb + mi) * 128 + t] = 1.f / (1.f + __expf(-s));
    }
}

// ============================================================================
extern "C" void kernel_launch(void* const* d_in, const int* in_sizes, int n_in,
                              void* d_out, int out_size)
{
    const float* x   = (const float*)d_in[0];
    const float* w1  = (const float*)d_in[1];
    const float* b1  = (const float*)d_in[2];
    const float* g1  = (const float*)d_in[3];
    const float* be1 = (const float*)d_in[4];
    const float* m1  = (const float*)d_in[5];
    const float* v1  = (const float*)d_in[6];
    const float* w2  = (const float*)d_in[7];
    const float* b2  = (const float*)d_in[8];
    const float* g2  = (const float*)d_in[9];
    const float* be2 = (const float*)d_in[10];
    const float* m2  = (const float*)d_in[11];
    const float* v2  = (const float*)d_in[12];
    const float* wa  = (const float*)d_in[13];
    const float* ba  = (const float*)d_in[14];
    const float* wd1 = (const float*)d_in[15];
    const float* bd1 = (const float*)d_in[16];
    const float* wd2 = (const float*)d_in[17];
    const float* bd2 = (const float*)d_in[18];
    float* out = (float*)d_out;

    const int conv2_smem = 33152 * 4;   // 132,608 B
    cudaFuncSetAttribute(conv2_fused_kernel,
                         cudaFuncAttributeMaxDynamicSharedMemorySize, conv2_smem);

    conv1_kernel<<<BATCH, 256>>>(x, w1, b1, g1, be1, m1, v1);
    conv2_fused_kernel<<<1036, 512, conv2_smem>>>(w2, b2, g2, be2, m2, v2, wa, ba);
    dim3 grid_fc1(64, 8);
    fc1_kernel<<<grid_fc1, 256>>>(wd1, bd1);
    fc2_kernel<<<BATCH / 16, 128>>>(wd2, bd2, out);
}

// round 2
// speedup vs baseline: 1.2628x; 1.2628x over previous
#include <cuda_runtime.h>
#include <math.h>
#include <stdint.h>

#define BN_EPS 1e-5f
#define BATCH 8192

// ---------------- scratch (device globals; no allocations allowed) ----------
__device__ float g_h[(size_t)BATCH * 32 * 16 * 16];   // conv1 output (268MB)
__device__ float g_f[(size_t)BATCH * 64 * 8 * 8];     // flattened feat, tf32-rounded (134MB)
__device__ float g_h1[(size_t)BATCH * 512];           // fc1 output (16MB)
__device__ float g_wd1[(size_t)512 * 4096];           // tf32-rounded wd1 (8MB)

__device__ __forceinline__ float to_tf32(float x) {
    uint32_t r;
    asm("cvt.rna.tf32.f32 %0, %1;" : "=r"(r) : "f"(x));
    return __uint_as_float(r);
}

// ============================================================================
// Kernel 0: round wd1 to tf32 once (RNA — avoids coherent truncation bias)
// ============================================================================
__global__ __launch_bounds__(256) void cvt_wd1_kernel(const float* __restrict__ wd1)
{
    int i = blockIdx.x * 256 + threadIdx.x;          // 524288 float4s
    float4 v = ((const float4*)wd1)[i];
    v.x = to_tf32(v.x); v.y = to_tf32(v.y);
    v.z = to_tf32(v.z); v.w = to_tf32(v.w);
    ((float4*)g_wd1)[i] = v;
}

// ============================================================================
// Kernel 1: conv1 (3->32, 5x5, stride2, pad2) + BN + ReLU.  One block/image.
// ============================================================================
__global__ __launch_bounds__(256) void conv1_kernel(
    const float* __restrict__ x, const float* __restrict__ w1,
    const float* __restrict__ b1, const float* __restrict__ g1,
    const float* __restrict__ be1, const float* __restrict__ m1,
    const float* __restrict__ v1)
{
    __shared__ float xs[3 * 32 * 32];
    __shared__ float ws[3 * 25 * 32];
    __shared__ float sc[32], bi[32];

    const int n = blockIdx.x;
    const int t = threadIdx.x;

    const float* xg = x + (size_t)n * 3072;
    for (int i = t; i < 3072; i += 256) xs[i] = xg[i];

    for (int i = t; i < 2400; i += 256) {
        int c = i / 75, r = i % 75;
        ws[r * 32 + c] = w1[i];
    }
    if (t < 32) {
        float s = g1[t] * rsqrtf(v1[t] + BN_EPS);
        sc[t] = s;
        bi[t] = be1[t] + (b1[t] - m1[t]) * s;
    }
    __syncthreads();

    const int oy = t >> 4, ox = t & 15;
    float acc[32];
#pragma unroll
    for (int c = 0; c < 32; c++) acc[c] = 0.f;

    for (int ky = 0; ky < 5; ky++) {
        int iy = oy * 2 - 2 + ky;
        if (iy < 0 || iy > 31) continue;
        for (int kx = 0; kx < 5; kx++) {
            int ix = ox * 2 - 2 + kx;
            if (ix < 0 || ix > 31) continue;
            float v0 = xs[          iy * 32 + ix];
            float va = xs[1024 +    iy * 32 + ix];
            float vb = xs[2048 +    iy * 32 + ix];
            const float* w0  = &ws[(      ky * 5 + kx) * 32];
            const float* w1p = &ws[(25  + ky * 5 + kx) * 32];
            const float* w2p = &ws[(50  + ky * 5 + kx) * 32];
#pragma unroll
            for (int c4 = 0; c4 < 8; c4++) {
                float4 wA = *(const float4*)(w0  + c4 * 4);
                float4 wB = *(const float4*)(w1p + c4 * 4);
                float4 wC = *(const float4*)(w2p + c4 * 4);
                acc[c4 * 4 + 0] += v0 * wA.x + va * wB.x + vb * wC.x;
                acc[c4 * 4 + 1] += v0 * wA.y + va * wB.y + vb * wC.y;
                acc[c4 * 4 + 2] += v0 * wA.z + va * wB.z + vb * wC.z;
                acc[c4 * 4 + 3] += v0 * wA.w + va * wB.w + vb * wC.w;
            }
        }
    }

    float* hg = g_h + (size_t)n * 8192;
#pragma unroll
    for (int c = 0; c < 32; c++) {
        float y = acc[c] * sc[c] + bi[c];
        hg[c * 256 + t] = fmaxf(y, 0.f);
    }
}

// ============================================================================
// Kernel 2: conv2 + BN + ReLU + Haar + attn, writes tf32-rounded feat
// ============================================================================
__global__ __launch_bounds__(512) void conv2_fused_kernel(
    const float* __restrict__ w2, const float* __restrict__ b2,
    const float* __restrict__ g2, const float* __restrict__ be2,
    const float* __restrict__ m2, const float* __restrict__ v2,
    const float* __restrict__ wa, const float* __restrict__ ba)
{
    extern __shared__ float sm[];
    float* hin  = sm;                // 10368
    float* ws   = sm + 10368;        // 18432
    float* feat = sm + 28800;        // 4096
    float* attn = sm + 32896;        // 64
    float* sc2  = sm + 32960;        // 64
    float* bi2  = sm + 33024;        // 64
    float* was  = sm + 33088;        // 64

    const int t = threadIdx.x;

    for (int i = t; i < 18432; i += 512) {
        int c = i / 288, r = i % 288;
        ws[r * 64 + c] = w2[i];
    }
    if (t < 64) {
        float s = g2[t] * rsqrtf(v2[t] + BN_EPS);
        sc2[t] = s;
        bi2[t] = be2[t] + (b2[t] - m2[t]) * s;
        was[t] = wa[t];
    }
    for (int i = t; i < 10368; i += 512) hin[i] = 0.f;
    const float bav = ba[0];
    __syncthreads();

    const int ct  = t >> 5;
    const int pt  = t & 31;
    const int c0  = ct * 4;
    const int oh  = pt >> 2;
    const int ow0 = (pt & 3) * 2;

    for (int n = blockIdx.x; n < BATCH; n += gridDim.x) {
        const float* hg = g_h + (size_t)n * 8192;
        for (int i = t; i < 8192; i += 512) {
            int ic = i >> 8, p = i & 255, y = p >> 4, xx = p & 15;
            hin[ic * 324 + (y + 1) * 18 + (xx + 1)] = hg[i];
        }
        __syncthreads();

        float acc00=0.f, acc01=0.f, acc10=0.f, acc11=0.f,
              acc20=0.f, acc21=0.f, acc30=0.f, acc31=0.f;

        for (int ic = 0; ic < 32; ic++) {
            const float* hi = hin + ic * 324;
            const float* wrow = ws + ic * 9 * 64 + c0;
#pragma unroll
            for (int kh = 0; kh < 3; kh++) {
                const float* hr = hi + (oh * 2 + kh) * 18 + ow0 * 2;
#pragma unroll
                for (int kw = 0; kw < 3; kw++) {
                    float4 w4 = *(const float4*)(wrow + (kh * 3 + kw) * 64);
                    float i0 = hr[kw];
                    float i1 = hr[kw + 2];
                    acc00 += w4.x * i0;  acc01 += w4.x * i1;
                    acc10 += w4.y * i0;  acc11 += w4.y * i1;
                    acc20 += w4.z * i0;  acc21 += w4.z * i1;
                    acc30 += w4.w * i0;  acc31 += w4.w * i1;
                }
            }
        }

        {
            int p = oh * 8 + ow0;
            float s0 = sc2[c0+0], s1 = sc2[c0+1], s2 = sc2[c0+2], s3 = sc2[c0+3];
            float t0 = bi2[c0+0], t1 = bi2[c0+1], t2 = bi2[c0+2], t3 = bi2[c0+3];
            feat[(c0+0)*64 + p    ] = fmaxf(acc00*s0 + t0, 0.f);
            feat[(c0+0)*64 + p + 1] = fmaxf(acc01*s0 + t0, 0.f);
            feat[(c0+1)*64 + p    ] = fmaxf(acc10*s1 + t1, 0.f);
            feat[(c0+1)*64 + p + 1] = fmaxf(acc11*s1 + t1, 0.f);
            feat[(c0+2)*64 + p    ] = fmaxf(acc20*s2 + t2, 0.f);
            feat[(c0+2)*64 + p + 1] = fmaxf(acc21*s2 + t2, 0.f);
            feat[(c0+3)*64 + p    ] = fmaxf(acc30*s3 + t3, 0.f);
            feat[(c0+3)*64 + p + 1] = fmaxf(acc31*s3 + t3, 0.f);
        }
        __syncthreads();

        for (int q = t; q < 1024; q += 512) {
            int c = q >> 4, blk = q & 15;
            int bI = blk >> 2, bJ = blk & 3;
            int p00 = c * 64 + (bI * 2) * 8 + bJ * 2;
            float a = feat[p00], b = feat[p00 + 1];
            float cc = feat[p00 + 8], d = feat[p00 + 9];
            float v = (a - b - cc + d) * 0.5f;
            feat[p00]     = a  * v;
            feat[p00 + 1] = b  * v;
            feat[p00 + 8] = cc * v;
            feat[p00 + 9] = d  * v;
        }
        __syncthreads();

        if (t < 64) {
            float s = bav;
            for (int c = 0; c < 64; c++) s += feat[c * 64 + t] * was[c];
            attn[t] = 1.f / (1.f + __expf(-s));
        }
        __syncthreads();

        float* fg = g_f + (size_t)n * 4096;
        for (int i = t; i < 4096; i += 512) {
            fg[i] = to_tf32(feat[i] * attn[i & 63]);   // pre-round for tf32 GEMM
        }
        __syncthreads();
    }
}

// ============================================================================
// Kernel 3: fc1  h1 = relu(f @ wd1^T + bd1)   — tf32 tensor-core GEMM
// M=8192 N=512 K=4096. Block 128x64, 8 warps (4Mx2N), warp 32x32, k16 steps.
// smem stride 24 -> conflict-free LDS.64 fragment loads.
// k-permutation: slot tg <-> mem 2tg, slot tg+4 <-> mem 2tg+1 (A & B identical).
// ============================================================================
__device__ __forceinline__ void mma_tf32(float* c, float2 a02, float2 a13, float2 b)
{
    asm volatile(
        "mma.sync.aligned.m16n8k8.row.col.f32.tf32.tf32.f32 "
        "{%0,%1,%2,%3}, {%4,%5,%6,%7}, {%8,%9}, {%0,%1,%2,%3};\n"
        : "+f"(c[0]), "+f"(c[1]), "+f"(c[2]), "+f"(c[3])
        : "r"(__float_as_uint(a02.x)), "r"(__float_as_uint(a13.x)),
          "r"(__float_as_uint(a02.y)), "r"(__float_as_uint(a13.y)),
          "r"(__float_as_uint(b.x)),   "r"(__float_as_uint(b.y)));
}

__global__ __launch_bounds__(256) void fc1_tf32_kernel(const float* __restrict__ bd1)
{
    __shared__ float As[2][128 * 24];
    __shared__ float Bs[2][64 * 24];

    const int t    = threadIdx.x;
    const int bn   = blockIdx.x;     // fastest -> A strip stays in L2
    const int bm   = blockIdx.y;
    const int w    = t >> 5, lane = t & 31;
    const int wm   = w >> 1, wn = w & 1;
    const int g    = lane >> 2, tg = lane & 3;

    const float* Ag = g_f   + (size_t)(bm * 128 + (t >> 1)) * 4096 + (t & 1) * 8;
    const float* Bg = g_wd1 + (size_t)(bn * 64  + (t >> 2)) * 4096 + (t & 3) * 4;
    const int asts = (t >> 1) * 24 + (t & 1) * 8;
    const int bsts = (t >> 2) * 24 + (t & 3) * 4;

    float4 a0r = *(const float4*)(Ag);
    float4 a1r = *(const float4*)(Ag + 4);
    float4 brr = *(const float4*)(Bg);
    *(float4*)&As[0][asts]     = a0r;
    *(float4*)&As[0][asts + 4] = a1r;
    *(float4*)&Bs[0][bsts]     = brr;
    __syncthreads();

    float acc[2][4][4];
#pragma unroll
    for (int mt = 0; mt < 2; mt++)
#pragma unroll
        for (int nt = 0; nt < 4; nt++)
#pragma unroll
            for (int i = 0; i < 4; i++) acc[mt][nt][i] = 0.f;

    const int arow = (wm * 32 + g) * 24;   // + mt*384, +192 for row+8
    const int brow = (wn * 32 + g) * 24;   // + nt*192

    for (int it = 0; it < 256; it++) {
        const int cur = it & 1;
        if (it < 255) {
            const float* Ap = Ag + (it + 1) * 16;
            a0r = *(const float4*)(Ap);
            a1r = *(const float4*)(Ap + 4);
            brr = *(const float4*)(Bg + (it + 1) * 16);
        }
        const float* A = As[cur];
        const float* B = Bs[cur];
#pragma unroll
        for (int kk = 0; kk < 16; kk += 8) {
            float2 af[2][2];
            float2 bf[4];
#pragma unroll
            for (int mt = 0; mt < 2; mt++) {
                af[mt][0] = *(const float2*)&A[arow + mt * 384       + kk + 2 * tg];
                af[mt][1] = *(const float2*)&A[arow + mt * 384 + 192 + kk + 2 * tg];
            }
#pragma unroll
            for (int nt = 0; nt < 4; nt++)
                bf[nt] = *(const float2*)&B[brow + nt * 192 + kk + 2 * tg];
#pragma unroll
            for (int mt = 0; mt < 2; mt++)
#pragma unroll
                for (int nt = 0; nt < 4; nt++)
                    mma_tf32(acc[mt][nt], af[mt][0], af[mt][1], bf[nt]);
        }
        if (it < 255) {
            __syncthreads();
            const int nxt = cur ^ 1;
            *(float4*)&As[nxt][asts]     = a0r;
            *(float4*)&As[nxt][asts + 4] = a1r;
            *(float4*)&Bs[nxt][bsts]     = brr;
            __syncthreads();
        }
    }

    // epilogue: bias + relu, c-fragment layout m16n8:
    //   c0,c1 -> row g,   cols 2tg, 2tg+1 ; c2,c3 -> row g+8
#pragma unroll
    for (int mt = 0; mt < 2; mt++) {
        const int m0 = bm * 128 + wm * 32 + mt * 16 + g;
#pragma unroll
        for (int nt = 0; nt < 4; nt++) {
            const int n0 = bn * 64 + wn * 32 + nt * 8 + 2 * tg;
            const float b0 = bd1[n0], b1 = bd1[n0 + 1];
            float2 r0, r1;
            r0.x = fmaxf(acc[mt][nt][0] + b0, 0.f);
            r0.y = fmaxf(acc[mt][nt][1] + b1, 0.f);
            r1.x = fmaxf(acc[mt][nt][2] + b0, 0.f);
            r1.y = fmaxf(acc[mt][nt][3] + b1, 0.f);
            *(float2*)&g_h1[(size_t)m0 * 512 + n0]       = r0;
            *(float2*)&g_h1[(size_t)(m0 + 8) * 512 + n0] = r1;
        }
    }
}

// ============================================================================
// Kernel 4: fc2  out = sigmoid(h1 @ wd2^T + bd2).  16 rows per block.
// ============================================================================
__global__ __launch_bounds__(128) void fc2_kernel(
    const float* __restrict__ wd2, const float* __restrict__ bd2,
    float* __restrict__ out)
{
    __shared__ float sh[16 * 512];
    const int mb = blockIdx.x * 16;
    const int t = threadIdx.x;

    const float4* src = (const float4*)(g_h1 + (size_t)mb * 512);
    for (int i = t; i < 16 * 512 / 4; i += 128)
        ((float4*)sh)[i] = src[i];
    __syncthreads();

    float acc[16];
#pragma unroll
    for (int i = 0; i < 16; i++) acc[i] = 0.f;

    const float* wr = wd2 + (size_t)t * 512;
#pragma unroll 2
    for (int k = 0; k < 512; k += 4) {
        float4 w = *(const float4*)&wr[k];
#pragma unroll
        for (int mi = 0; mi < 16; mi++) {
            float4 hv = *(const float4*)&sh[mi * 512 + k];
            acc[mi] += hv.x * w.x + hv.y * w.y + hv.z * w.z + hv.w * w.w;
        }
    }

    const float b = bd2[t];
#pragma unroll
    for (int mi = 0; mi < 16; mi++) {
        float s = acc[mi] + b;
        out[(size_t)(mb + mi) * 128 + t] = 1.f / (1.f + __expf(-s));
    }
}

// ============================================================================
extern "C" void kernel_launch(void* const* d_in, const int* in_sizes, int n_in,
                              void* d_out, int out_size)
{
    const float* x   = (const float*)d_in[0];
    const float* w1  = (const float*)d_in[1];
    const float* b1  = (const float*)d_in[2];
    const float* g1  = (const float*)d_in[3];
    const float* be1 = (const float*)d_in[4];
    const float* m1  = (const float*)d_in[5];
    const float* v1  = (const float*)d_in[6];
    const float* w2  = (const float*)d_in[7];
    const float* b2  = (const float*)d_in[8];
    const float* g2  = (const float*)d_in[9];
    const float* be2 = (const float*)d_in[10];
    const float* m2  = (const float*)d_in[11];
    const float* v2  = (const float*)d_in[12];
    const float* wa  = (const float*)d_in[13];
    const float* ba  = (const float*)d_in[14];
    const float* wd1 = (const float*)d_in[15];
    const float* bd1 = (const float*)d_in[16];
    const float* wd2 = (const float*)d_in[17];
    const float* bd2 = (const float*)d_in[18];
    float* out = (float*)d_out;

    const int conv2_smem = 33152 * 4;
    cudaFuncSetAttribute(conv2_fused_kernel,
                         cudaFuncAttributeMaxDynamicSharedMemorySize, conv2_smem);

    cvt_wd1_kernel<<<2048, 256>>>(wd1);
    conv1_kernel<<<BATCH, 256>>>(x, w1, b1, g1, be1, m1, v1);
    conv2_fused_kernel<<<1036, 512, conv2_smem>>>(w2, b2, g2, be2, m2, v2, wa, ba);
    dim3 grid_fc1(8, 64);
    fc1_tf32_kernel<<<grid_fc1, 256>>>(bd1);
    fc2_kernel<<<BATCH / 16, 128>>>(wd2, bd2, out);
}

// round 3
// speedup vs baseline: 1.8815x; 1.4900x over previous
#include <cuda_runtime.h>
#include <math.h>
#include <stdint.h>

#define BN_EPS 1e-5f
#define BATCH 8192

// ---------------- scratch (device globals; no allocations allowed) ----------
__device__ float g_h[(size_t)BATCH * 32 * 16 * 16];   // conv1 output, HWC tf32 (268MB)
__device__ float g_f[(size_t)BATCH * 64 * 8 * 8];     // flattened feat, tf32 (134MB)
__device__ float g_h1[(size_t)BATCH * 512];           // fc1 output (16MB)
__device__ float g_wd1[(size_t)512 * 4096];           // tf32 wd1 (8MB)
__device__ float g_wq[(size_t)9 * 64 * 36];           // conv2 weights [q][oc][ic(pad36)] tf32

__device__ __forceinline__ float to_tf32(float x) {
    uint32_t r;
    asm("cvt.rna.tf32.f32 %0, %1;" : "=r"(r) : "f"(x));
    return __uint_as_float(r);
}

// ============================================================================
// Kernel 0a: round wd1 to tf32 once
// ============================================================================
__global__ __launch_bounds__(256) void cvt_wd1_kernel(const float* __restrict__ wd1)
{
    int i = blockIdx.x * 256 + threadIdx.x;
    float4 v = ((const float4*)wd1)[i];
    v.x = to_tf32(v.x); v.y = to_tf32(v.y);
    v.z = to_tf32(v.z); v.w = to_tf32(v.w);
    ((float4*)g_wd1)[i] = v;
}

// ============================================================================
// Kernel 0b: reorder w2 (oc,ic,3,3) -> g_wq[q][oc][ic] (row stride 36), tf32
// ============================================================================
__global__ __launch_bounds__(256) void cvt_w2_kernel(const float* __restrict__ w2)
{
    int i = blockIdx.x * 256 + threadIdx.x;   // 18432 = 64*32*9
    if (i >= 18432) return;
    int oc = i / 288;
    int rem = i % 288;
    int ic = rem / 9;
    int q  = rem % 9;
    g_wq[(q * 64 + oc) * 36 + ic] = to_tf32(w2[i]);
}

// ============================================================================
// Kernel 1: conv1 (3->32, 5x5, s2, p2) + BN + ReLU -> HWC tf32.  One block/image.
// ============================================================================
__global__ __launch_bounds__(256) void conv1_kernel(
    const float* __restrict__ x, const float* __restrict__ w1,
    const float* __restrict__ b1, const float* __restrict__ g1,
    const float* __restrict__ be1, const float* __restrict__ m1,
    const float* __restrict__ v1)
{
    __shared__ float xs[3 * 32 * 32];
    __shared__ float ws[3 * 25 * 32];
    __shared__ float sc[32], bi[32];

    const int n = blockIdx.x;
    const int t = threadIdx.x;

    const float* xg = x + (size_t)n * 3072;
    for (int i = t; i < 3072; i += 256) xs[i] = xg[i];

    for (int i = t; i < 2400; i += 256) {
        int c = i / 75, r = i % 75;
        ws[r * 32 + c] = w1[i];
    }
    if (t < 32) {
        float s = g1[t] * rsqrtf(v1[t] + BN_EPS);
        sc[t] = s;
        bi[t] = be1[t] + (b1[t] - m1[t]) * s;
    }
    __syncthreads();

    const int oy = t >> 4, ox = t & 15;
    float acc[32];
#pragma unroll
    for (int c = 0; c < 32; c++) acc[c] = 0.f;

    for (int ky = 0; ky < 5; ky++) {
        int iy = oy * 2 - 2 + ky;
        if (iy < 0 || iy > 31) continue;
        for (int kx = 0; kx < 5; kx++) {
            int ix = ox * 2 - 2 + kx;
            if (ix < 0 || ix > 31) continue;
            float v0 = xs[          iy * 32 + ix];
            float va = xs[1024 +    iy * 32 + ix];
            float vb = xs[2048 +    iy * 32 + ix];
            const float* w0  = &ws[(      ky * 5 + kx) * 32];
            const float* w1p = &ws[(25  + ky * 5 + kx) * 32];
            const float* w2p = &ws[(50  + ky * 5 + kx) * 32];
#pragma unroll
            for (int c4 = 0; c4 < 8; c4++) {
                float4 wA = *(const float4*)(w0  + c4 * 4);
                float4 wB = *(const float4*)(w1p + c4 * 4);
                float4 wC = *(const float4*)(w2p + c4 * 4);
                acc[c4 * 4 + 0] += v0 * wA.x + va * wB.x + vb * wC.x;
                acc[c4 * 4 + 1] += v0 * wA.y + va * wB.y + vb * wC.y;
                acc[c4 * 4 + 2] += v0 * wA.z + va * wB.z + vb * wC.z;
                acc[c4 * 4 + 3] += v0 * wA.w + va * wB.w + vb * wC.w;
            }
        }
    }

    // HWC write: hg[pos*32 + c], pos = t, tf32-rounded (feeds conv2 mma only)
    float* hg = g_h + (size_t)n * 8192 + (size_t)t * 32;
#pragma unroll
    for (int c4 = 0; c4 < 8; c4++) {
        float4 o;
        o.x = to_tf32(fmaxf(acc[c4*4+0] * sc[c4*4+0] + bi[c4*4+0], 0.f));
        o.y = to_tf32(fmaxf(acc[c4*4+1] * sc[c4*4+1] + bi[c4*4+1], 0.f));
        o.z = to_tf32(fmaxf(acc[c4*4+2] * sc[c4*4+2] + bi[c4*4+2], 0.f));
        o.w = to_tf32(fmaxf(acc[c4*4+3] * sc[c4*4+3] + bi[c4*4+3], 0.f));
        *(float4*)&hg[c4 * 4] = o;
    }
}

// ============================================================================
// Kernel 2: conv2 via tensor cores (tf32 mma) + BN + ReLU + Haar + attn.
// Per image: C[64 pos][64 oc] = sum_q patch_q[pos][32ic] * Wq[oc][32ic].
// Block = 256 threads = 2 groups x 4 warps, one image per group, persistent.
// smem floats: wq 20736 | hwc 2x11664 | feat 2x4096 | attn 2x64 | sc/bi/was 192
// ============================================================================
__device__ __forceinline__ void mma_tf32(float* c, float2 a02, float2 a13, float2 b)
{
    asm volatile(
        "mma.sync.aligned.m16n8k8.row.col.f32.tf32.tf32.f32 "
        "{%0,%1,%2,%3}, {%4,%5,%6,%7}, {%8,%9}, {%0,%1,%2,%3};\n"
        : "+f"(c[0]), "+f"(c[1]), "+f"(c[2]), "+f"(c[3])
        : "r"(__float_as_uint(a02.x)), "r"(__float_as_uint(a13.x)),
          "r"(__float_as_uint(a02.y)), "r"(__float_as_uint(a13.y)),
          "r"(__float_as_uint(b.x)),   "r"(__float_as_uint(b.y)));
}

#define C2_SMEM_FLOATS 52576

__global__ __launch_bounds__(256) void conv2_mma_kernel(
    const float* __restrict__ b2, const float* __restrict__ g2,
    const float* __restrict__ be2, const float* __restrict__ m2,
    const float* __restrict__ v2, const float* __restrict__ wa,
    const float* __restrict__ ba)
{
    extern __shared__ float sm[];
    float* wq    = sm;                 // 20736
    float* hwcs  = sm + 20736;         // 2 * 11664 (324 rows * 36)
    float* feats = sm + 44064;         // 2 * 4096
    float* attn  = sm + 52256;         // 2 * 64
    float* sc2   = sm + 52384;         // 64
    float* bi2   = sm + 52448;         // 64
    float* was   = sm + 52512;         // 64

    const int t = threadIdx.x;

    for (int i = t; i < 20736; i += 256) wq[i] = g_wq[i];
    for (int i = t; i < 23328; i += 256) hwcs[i] = 0.f;   // borders stay zero
    if (t < 64) {
        float s = g2[t] * rsqrtf(v2[t] + BN_EPS);
        sc2[t] = s;
        bi2[t] = be2[t] + (b2[t] - m2[t]) * s;
        was[t] = wa[t];
    }
    const float bav = ba[0];
    __syncthreads();

    const int grp  = t >> 7;          // image within pair
    const int u    = t & 127;
    const int w4   = u >> 5;
    const int lane = u & 31;
    const int wm   = w4 >> 1, wn = w4 & 1;   // 2x2 warp grid (32pos x 32oc each)
    const int g    = lane >> 2, tg = lane & 3;

    float* hwc  = hwcs  + grp * 11664;
    float* feat = feats + grp * 4096;

    // A base rows: row = 2*oh*18 + 2*ow = 36*oh + 2*ow,  m = pos index
    int baseA[2][2];
#pragma unroll
    for (int mt = 0; mt < 2; mt++)
#pragma unroll
        for (int r = 0; r < 2; r++) {
            int m = wm * 32 + mt * 16 + g + 8 * r;
            baseA[mt][r] = 36 * (m >> 3) + 2 * (m & 7);
        }

    for (int n0 = blockIdx.x * 2; n0 < BATCH; n0 += gridDim.x * 2) {
        const int n = n0 + grp;

        // load image (HWC, contiguous) -> padded hwc smem
        const float4* src = (const float4*)(g_h + (size_t)n * 8192);
        for (int i = u; i < 2048; i += 128) {
            int p = i >> 3, ic4 = (i & 7) * 4;
            int y = p >> 4, xx = p & 15;
            *(float4*)&hwc[((y + 1) * 18 + xx + 1) * 36 + ic4] = src[i];
        }
        __syncthreads();

        float acc[2][4][4];
#pragma unroll
        for (int mt = 0; mt < 2; mt++)
#pragma unroll
            for (int nt = 0; nt < 4; nt++)
#pragma unroll
                for (int i = 0; i < 4; i++) acc[mt][nt][i] = 0.f;

        for (int q = 0; q < 9; q++) {
            const int kh = q / 3, kw = q - kh * 3;
            const int dq = kh * 18 + kw;
            const float* A00 = hwc + (baseA[0][0] + dq) * 36 + 2 * tg;
            const float* A01 = hwc + (baseA[0][1] + dq) * 36 + 2 * tg;
            const float* A10 = hwc + (baseA[1][0] + dq) * 36 + 2 * tg;
            const float* A11 = hwc + (baseA[1][1] + dq) * 36 + 2 * tg;
            const float* Bq  = wq + (q * 64 + wn * 32 + g) * 36 + 2 * tg;
#pragma unroll
            for (int kk = 0; kk < 32; kk += 8) {
                float2 af[2][2], bf[4];
                af[0][0] = *(const float2*)(A00 + kk);
                af[0][1] = *(const float2*)(A01 + kk);
                af[1][0] = *(const float2*)(A10 + kk);
                af[1][1] = *(const float2*)(A11 + kk);
#pragma unroll
                for (int nt = 0; nt < 4; nt++)
                    bf[nt] = *(const float2*)(Bq + nt * (8 * 36) + kk);
#pragma unroll
                for (int mt = 0; mt < 2; mt++)
#pragma unroll
                    for (int nt = 0; nt < 4; nt++)
                        mma_tf32(acc[mt][nt], af[mt][0], af[mt][1], bf[nt]);
            }
        }

        // epilogue: BN + ReLU -> feat[oc][pos]
#pragma unroll
        for (int mt = 0; mt < 2; mt++) {
            const int m0 = wm * 32 + mt * 16 + g;
#pragma unroll
            for (int nt = 0; nt < 4; nt++) {
                const int c0 = wn * 32 + nt * 8 + 2 * tg;
                float s0 = sc2[c0], s1 = sc2[c0 + 1];
                float t0 = bi2[c0], t1 = bi2[c0 + 1];
                feat[c0 * 64 + m0]           = fmaxf(acc[mt][nt][0] * s0 + t0, 0.f);
                feat[(c0 + 1) * 64 + m0]     = fmaxf(acc[mt][nt][1] * s1 + t1, 0.f);
                feat[c0 * 64 + m0 + 8]       = fmaxf(acc[mt][nt][2] * s0 + t0, 0.f);
                feat[(c0 + 1) * 64 + m0 + 8] = fmaxf(acc[mt][nt][3] * s1 + t1, 0.f);
            }
        }
        __syncthreads();

        // Haar cD * upsample (per group)
        for (int qq = u; qq < 1024; qq += 128) {
            int c = qq >> 4, blk = qq & 15;
            int bI = blk >> 2, bJ = blk & 3;
            int p00 = c * 64 + (bI * 2) * 8 + bJ * 2;
            float a = feat[p00], b = feat[p00 + 1];
            float cc = feat[p00 + 8], d = feat[p00 + 9];
            float v = (a - b - cc + d) * 0.5f;
            feat[p00]     = a  * v;
            feat[p00 + 1] = b  * v;
            feat[p00 + 8] = cc * v;
            feat[p00 + 9] = d  * v;
        }
        __syncthreads();

        // 1x1 attn + sigmoid
        if (u < 64) {
            float s = bav;
            for (int c = 0; c < 64; c++) s += feat[c * 64 + u] * was[c];
            attn[grp * 64 + u] = 1.f / (1.f + __expf(-s));
        }
        __syncthreads();

        // multiply & store tf32 (feeds fc1 mma)
        float* fg = g_f + (size_t)n * 4096;
        for (int i = u; i < 4096; i += 128)
            fg[i] = to_tf32(feat[i] * attn[grp * 64 + (i & 63)]);
        __syncthreads();
    }
}

// ============================================================================
// Kernel 3: fc1  h1 = relu(f @ wd1^T + bd1)   — tf32 tensor-core GEMM
// ============================================================================
__global__ __launch_bounds__(256) void fc1_tf32_kernel(const float* __restrict__ bd1)
{
    __shared__ float As[2][128 * 24];
    __shared__ float Bs[2][64 * 24];

    const int t    = threadIdx.x;
    const int bn   = blockIdx.x;
    const int bm   = blockIdx.y;
    const int w    = t >> 5, lane = t & 31;
    const int wm   = w >> 1, wn = w & 1;
    const int g    = lane >> 2, tg = lane & 3;

    const float* Ag = g_f   + (size_t)(bm * 128 + (t >> 1)) * 4096 + (t & 1) * 8;
    const float* Bg = g_wd1 + (size_t)(bn * 64  + (t >> 2)) * 4096 + (t & 3) * 4;
    const int asts = (t >> 1) * 24 + (t & 1) * 8;
    const int bsts = (t >> 2) * 24 + (t & 3) * 4;

    float4 a0r = *(const float4*)(Ag);
    float4 a1r = *(const float4*)(Ag + 4);
    float4 brr = *(const float4*)(Bg);
    *(float4*)&As[0][asts]     = a0r;
    *(float4*)&As[0][asts + 4] = a1r;
    *(float4*)&Bs[0][bsts]     = brr;
    __syncthreads();

    float acc[2][4][4];
#pragma unroll
    for (int mt = 0; mt < 2; mt++)
#pragma unroll
        for (int nt = 0; nt < 4; nt++)
#pragma unroll
            for (int i = 0; i < 4; i++) acc[mt][nt][i] = 0.f;

    const int arow = (wm * 32 + g) * 24;
    const int brow = (wn * 32 + g) * 24;

    for (int it = 0; it < 256; it++) {
        const int cur = it & 1;
        if (it < 255) {
            const float* Ap = Ag + (it + 1) * 16;
            a0r = *(const float4*)(Ap);
            a1r = *(const float4*)(Ap + 4);
            brr = *(const float4*)(Bg + (it + 1) * 16);
        }
        const float* A = As[cur];
        const float* B = Bs[cur];
#pragma unroll
        for (int kk = 0; kk < 16; kk += 8) {
            float2 af[2][2];
            float2 bf[4];
#pragma unroll
            for (int mt = 0; mt < 2; mt++) {
                af[mt][0] = *(const float2*)&A[arow + mt * 384       + kk + 2 * tg];
                af[mt][1] = *(const float2*)&A[arow + mt * 384 + 192 + kk + 2 * tg];
            }
#pragma unroll
            for (int nt = 0; nt < 4; nt++)
                bf[nt] = *(const float2*)&B[brow + nt * 192 + kk + 2 * tg];
#pragma unroll
            for (int mt = 0; mt < 2; mt++)
#pragma unroll
                for (int nt = 0; nt < 4; nt++)
                    mma_tf32(acc[mt][nt], af[mt][0], af[mt][1], bf[nt]);
        }
        if (it < 255) {
            __syncthreads();
            const int nxt = cur ^ 1;
            *(float4*)&As[nxt][asts]     = a0r;
            *(float4*)&As[nxt][asts + 4] = a1r;
            *(float4*)&Bs[nxt][bsts]     = brr;
            __syncthreads();
        }
    }

#pragma unroll
    for (int mt = 0; mt < 2; mt++) {
        const int m0 = bm * 128 + wm * 32 + mt * 16 + g;
#pragma unroll
        for (int nt = 0; nt < 4; nt++) {
            const int n0 = bn * 64 + wn * 32 + nt * 8 + 2 * tg;
            const float b0 = bd1[n0], b1 = bd1[n0 + 1];
            float2 r0, r1;
            r0.x = fmaxf(acc[mt][nt][0] + b0, 0.f);
            r0.y = fmaxf(acc[mt][nt][1] + b1, 0.f);
            r1.x = fmaxf(acc[mt][nt][2] + b0, 0.f);
            r1.y = fmaxf(acc[mt][nt][3] + b1, 0.f);
            *(float2*)&g_h1[(size_t)m0 * 512 + n0]       = r0;
            *(float2*)&g_h1[(size_t)(m0 + 8) * 512 + n0] = r1;
        }
    }
}

// ============================================================================
// Kernel 4: fc2  out = sigmoid(h1 @ wd2^T + bd2).  16 rows per block.
// ============================================================================
__global__ __launch_bounds__(128) void fc2_kernel(
    const float* __restrict__ wd2, const float* __restrict__ bd2,
    float* __restrict__ out)
{
    __shared__ float sh[16 * 512];
    const int mb = blockIdx.x * 16;
    const int t = threadIdx.x;

    const float4* src = (const float4*)(g_h1 + (size_t)mb * 512);
    for (int i = t; i < 16 * 512 / 4; i += 128)
        ((float4*)sh)[i] = src[i];
    __syncthreads();

    float acc[16];
#pragma unroll
    for (int i = 0; i < 16; i++) acc[i] = 0.f;

    const float* wr = wd2 + (size_t)t * 512;
#pragma unroll 2
    for (int k = 0; k < 512; k += 4) {
        float4 w = *(const float4*)&wr[k];
#pragma unroll
        for (int mi = 0; mi < 16; mi++) {
            float4 hv = *(const float4*)&sh[mi * 512 + k];
            acc[mi] += hv.x * w.x + hv.y * w.y + hv.z * w.z + hv.w * w.w;
        }
    }

    const float b = bd2[t];
#pragma unroll
    for (int mi = 0; mi < 16; mi++) {
        float s = acc[mi] + b;
        out[(size_t)(mb + mi) * 128 + t] = 1.f / (1.f + __expf(-s));
    }
}

// ============================================================================
extern "C" void kernel_launch(void* const* d_in, const int* in_sizes, int n_in,
                              void* d_out, int out_size)
{
    const float* x   = (const float*)d_in[0];
    const float* w1  = (const float*)d_in[1];
    const float* b1  = (const float*)d_in[2];
    const float* g1  = (const float*)d_in[3];
    const float* be1 = (const float*)d_in[4];
    const float* m1  = (const float*)d_in[5];
    const float* v1  = (const float*)d_in[6];
    const float* w2  = (const float*)d_in[7];
    const float* b2  = (const float*)d_in[8];
    const float* g2  = (const float*)d_in[9];
    const float* be2 = (const float*)d_in[10];
    const float* m2  = (const float*)d_in[11];
    const float* v2  = (const float*)d_in[12];
    const float* wa  = (const float*)d_in[13];
    const float* ba  = (const float*)d_in[14];
    const float* wd1 = (const float*)d_in[15];
    const float* bd1 = (const float*)d_in[16];
    const float* wd2 = (const float*)d_in[17];
    const float* bd2 = (const float*)d_in[18];
    float* out = (float*)d_out;

    const int conv2_smem = C2_SMEM_FLOATS * 4;   // 210,304 B
    cudaFuncSetAttribute(conv2_mma_kernel,
                         cudaFuncAttributeMaxDynamicSharedMemorySize, conv2_smem);

    cvt_wd1_kernel<<<2048, 256>>>(wd1);
    cvt_w2_kernel<<<72, 256>>>(w2);
    conv1_kernel<<<BATCH, 256>>>(x, w1, b1, g1, be1, m1, v1);
    conv2_mma_kernel<<<148, 256, conv2_smem>>>(b2, g2, be2, m2, v2, wa, ba);
    dim3 grid_fc1(8, 64);
    fc1_tf32_kernel<<<grid_fc1, 256>>>(bd1);
    fc2_kernel<<<BATCH / 16, 128>>>(wd2, bd2, out);
}

// round 6
// speedup vs baseline: 2.7228x; 1.4472x over previous
#include <cuda_runtime.h>
#include <math.h>
#include <stdint.h>

#define BN_EPS 1e-5f
#define BATCH 8192

// ---------------- scratch (device globals; no allocations allowed) ----------
__device__ float g_h[(size_t)BATCH * 32 * 16 * 16];   // conv1 output, HWC tf32 (268MB)
__device__ float g_f[(size_t)BATCH * 64 * 8 * 8];     // flattened feat, tf32 (134MB)
__device__ float g_h1[(size_t)BATCH * 512];           // fc1 output, tf32 (16MB)
__device__ float g_wd1[(size_t)512 * 4096];           // tf32 wd1 (8MB)
__device__ float g_wd2t[(size_t)128 * 512];           // tf32 wd2
__device__ float g_wq[(size_t)9 * 64 * 36];           // conv2 W [q][oc][ic pad36] tf32
__device__ float g_w1q[(size_t)15 * 32 * 8];          // conv1 W [ic*5+ky][oc][kx pad8] tf32

__device__ __forceinline__ float to_tf32(float x) {
    uint32_t r;
    asm("cvt.rna.tf32.f32 %0, %1;" : "=r"(r) : "f"(x));
    return __uint_as_float(r);
}

__device__ __forceinline__ void mma_tf32(float* c, float2 a02, float2 a13, float2 b)
{
    asm volatile(
        "mma.sync.aligned.m16n8k8.row.col.f32.tf32.tf32.f32 "
        "{%0,%1,%2,%3}, {%4,%5,%6,%7}, {%8,%9}, {%0,%1,%2,%3};\n"
        : "+f"(c[0]), "+f"(c[1]), "+f"(c[2]), "+f"(c[3])
        : "r"(__float_as_uint(a02.x)), "r"(__float_as_uint(a13.x)),
          "r"(__float_as_uint(a02.y)), "r"(__float_as_uint(a13.y)),
          "r"(__float_as_uint(b.x)),   "r"(__float_as_uint(b.y)));
}

// ============================================================================
// Prep kernels (all write device globals from DEVICE code — legal)
// ============================================================================
__global__ __launch_bounds__(256) void cvt_wd1_kernel(const float* __restrict__ wd1)
{
    int i = blockIdx.x * 256 + threadIdx.x;          // 524288 float4
    float4 v = ((const float4*)wd1)[i];
    v.x = to_tf32(v.x); v.y = to_tf32(v.y);
    v.z = to_tf32(v.z); v.w = to_tf32(v.w);
    ((float4*)g_wd1)[i] = v;
}

__global__ __launch_bounds__(256) void cvt_wd2_kernel(const float* __restrict__ wd2)
{
    int i = blockIdx.x * 256 + threadIdx.x;          // 16384 float4
    float4 v = ((const float4*)wd2)[i];
    v.x = to_tf32(v.x); v.y = to_tf32(v.y);
    v.z = to_tf32(v.z); v.w = to_tf32(v.w);
    ((float4*)g_wd2t)[i] = v;
}

__global__ __launch_bounds__(256) void cvt_w2_kernel(const float* __restrict__ w2)
{
    int i = blockIdx.x * 256 + threadIdx.x;   // 18432 = 64*32*9
    if (i >= 18432) return;
    int oc = i / 288;
    int rem = i % 288;
    int ic = rem / 9;
    int q  = rem % 9;
    g_wq[(q * 64 + oc) * 36 + ic] = to_tf32(w2[i]);
}

// w1 (oc,ic,5,5) -> g_w1q[(ic*5+ky)][oc][kx], kx padded to 8 with zeros
__global__ __launch_bounds__(256) void cvt_w1_kernel(const float* __restrict__ w1)
{
    int i = blockIdx.x * 256 + threadIdx.x;   // 15*32*8 = 3840
    if (i >= 3840) return;
    int tap = i >> 8;              // ic*5+ky
    int oc  = (i >> 3) & 31;
    int kx  = i & 7;
    int ic  = tap / 5, ky = tap % 5;
    float v = (kx < 5) ? w1[oc * 75 + ic * 25 + ky * 5 + kx] : 0.f;
    g_w1q[i] = to_tf32(v);
}

// ============================================================================
// Kernel 1: conv1 via tensor cores. One block (128 thr, 4 warps) per image.
// For each tap (ic,ky): C[256 pos][32 oc] += A_win * W_tap^T, where A rows are
// contiguous 8-float windows of the padded input row (k = kx padded to 8).
// xs padded: [3][36 rows][38 cols].
// ============================================================================
__global__ __launch_bounds__(128) void conv1_mma_kernel(
    const float* __restrict__ x,
    const float* __restrict__ b1, const float* __restrict__ g1,
    const float* __restrict__ be1, const float* __restrict__ m1,
    const float* __restrict__ v1)
{
    __shared__ float xs[3 * 36 * 38];    // 4104 floats
    __shared__ float wb[15 * 32 * 8];    // 3840 floats
    __shared__ float sc[32], bi[32];

    const int n = blockIdx.x;
    const int t = threadIdx.x;
    const int w = t >> 5, lane = t & 31;
    const int g = lane >> 2, tg = lane & 3;

    for (int i = t; i < 4104; i += 128) xs[i] = 0.f;
    for (int i = t; i < 3840; i += 128) wb[i] = g_w1q[i];
    if (t < 32) {
        float s = g1[t] * rsqrtf(v1[t] + BN_EPS);
        sc[t] = s;
        bi[t] = be1[t] + (b1[t] - m1[t]) * s;
    }
    __syncthreads();

    const float* xg = x + (size_t)n * 3072;
    for (int i = t; i < 3072; i += 128) {
        int ic = i >> 10, rem = i & 1023;
        int iy = rem >> 5, ix = rem & 31;
        xs[ic * 1368 + (iy + 2) * 38 + ix + 2] = to_tf32(xg[i]);
    }
    __syncthreads();

    float acc[4][4][4];
#pragma unroll
    for (int mt = 0; mt < 4; mt++)
#pragma unroll
        for (int nt = 0; nt < 4; nt++)
#pragma unroll
            for (int i = 0; i < 4; i++) acc[mt][nt][i] = 0.f;

#pragma unroll
    for (int tap = 0; tap < 15; tap++) {
        const int ic = tap / 5, ky = tap % 5;
        const float* Bp = wb + tap * 256 + g * 8 + 2 * tg;
        float2 bf[4];
#pragma unroll
        for (int nt = 0; nt < 4; nt++)
            bf[nt] = *(const float2*)(Bp + nt * 64);
#pragma unroll
        for (int mt = 0; mt < 4; mt++) {
            const int oy = (w << 2) + mt;
            const float* Ap = xs + ic * 1368 + (2 * oy + ky) * 38 + 2 * tg;
            float2 a0 = *(const float2*)(Ap + 2 * g);        // pos ox=g
            float2 a1 = *(const float2*)(Ap + 2 * g + 16);   // pos ox=g+8
#pragma unroll
            for (int nt = 0; nt < 4; nt++)
                mma_tf32(acc[mt][nt], a0, a1, bf[nt]);
        }
    }

    // epilogue: BN + ReLU + tf32 round, write HWC  g_h[n][pos][oc]
    float* hg = g_h + (size_t)n * 8192;
#pragma unroll
    for (int mt = 0; mt < 4; mt++) {
        const int oy = (w << 2) + mt;
#pragma unroll
        for (int nt = 0; nt < 4; nt++) {
            const int oc = nt * 8 + 2 * tg;
            const float s0 = sc[oc], s1 = sc[oc + 1];
            const float t0 = bi[oc], t1 = bi[oc + 1];
            float2 r0, r1;
            r0.x = to_tf32(fmaxf(acc[mt][nt][0] * s0 + t0, 0.f));
            r0.y = to_tf32(fmaxf(acc[mt][nt][1] * s1 + t1, 0.f));
            r1.x = to_tf32(fmaxf(acc[mt][nt][2] * s0 + t0, 0.f));
            r1.y = to_tf32(fmaxf(acc[mt][nt][3] * s1 + t1, 0.f));
            *(float2*)&hg[(oy * 16 + g) * 32 + oc]     = r0;
            *(float2*)&hg[(oy * 16 + g + 8) * 32 + oc] = r1;
        }
    }
}

// ============================================================================
// Kernel 2: conv2 via tensor cores + BN + ReLU + Haar + attn (PROVEN R3)
// ============================================================================
#define C2_SMEM_FLOATS 52576

__global__ __launch_bounds__(256) void conv2_mma_kernel(
    const float* __restrict__ b2, const float* __restrict__ g2,
    const float* __restrict__ be2, const float* __restrict__ m2,
    const float* __restrict__ v2, const float* __restrict__ wa,
    const float* __restrict__ ba)
{
    extern __shared__ float sm[];
    float* wq    = sm;                 // 20736
    float* hwcs  = sm + 20736;         // 2 * 11664 (324 rows * 36)
    float* feats = sm + 44064;         // 2 * 4096
    float* attn  = sm + 52256;         // 2 * 64
    float* sc2   = sm + 52384;
    float* bi2   = sm + 52448;
    float* was   = sm + 52512;

    const int t = threadIdx.x;

    for (int i = t; i < 20736; i += 256) wq[i] = g_wq[i];
    for (int i = t; i < 23328; i += 256) hwcs[i] = 0.f;
    if (t < 64) {
        float s = g2[t] * rsqrtf(v2[t] + BN_EPS);
        sc2[t] = s;
        bi2[t] = be2[t] + (b2[t] - m2[t]) * s;
        was[t] = wa[t];
    }
    const float bav = ba[0];
    __syncthreads();

    const int grp  = t >> 7;
    const int u    = t & 127;
    const int w4   = u >> 5;
    const int lane = u & 31;
    const int wm   = w4 >> 1, wn = w4 & 1;
    const int g    = lane >> 2, tg = lane & 3;

    float* hwc  = hwcs  + grp * 11664;
    float* feat = feats + grp * 4096;

    int baseA[2][2];
#pragma unroll
    for (int mt = 0; mt < 2; mt++)
#pragma unroll
        for (int r = 0; r < 2; r++) {
            int m = wm * 32 + mt * 16 + g + 8 * r;
            baseA[mt][r] = 36 * (m >> 3) + 2 * (m & 7);
        }

    for (int n0 = blockIdx.x * 2; n0 < BATCH; n0 += gridDim.x * 2) {
        const int n = n0 + grp;

        const float4* src = (const float4*)(g_h + (size_t)n * 8192);
        for (int i = u; i < 2048; i += 128) {
            int p = i >> 3, ic4 = (i & 7) * 4;
            int y = p >> 4, xx = p & 15;
            *(float4*)&hwc[((y + 1) * 18 + xx + 1) * 36 + ic4] = src[i];
        }
        __syncthreads();

        float acc[2][4][4];
#pragma unroll
        for (int mt = 0; mt < 2; mt++)
#pragma unroll
            for (int nt = 0; nt < 4; nt++)
#pragma unroll
                for (int i = 0; i < 4; i++) acc[mt][nt][i] = 0.f;

        for (int q = 0; q < 9; q++) {
            const int kh = q / 3, kw = q - kh * 3;
            const int dq = kh * 18 + kw;
            const float* A00 = hwc + (baseA[0][0] + dq) * 36 + 2 * tg;
            const float* A01 = hwc + (baseA[0][1] + dq) * 36 + 2 * tg;
            const float* A10 = hwc + (baseA[1][0] + dq) * 36 + 2 * tg;
            const float* A11 = hwc + (baseA[1][1] + dq) * 36 + 2 * tg;
            const float* Bq  = wq + (q * 64 + wn * 32 + g) * 36 + 2 * tg;
#pragma unroll
            for (int kk = 0; kk < 32; kk += 8) {
                float2 af[2][2], bf[4];
                af[0][0] = *(const float2*)(A00 + kk);
                af[0][1] = *(const float2*)(A01 + kk);
                af[1][0] = *(const float2*)(A10 + kk);
                af[1][1] = *(const float2*)(A11 + kk);
#pragma unroll
                for (int nt = 0; nt < 4; nt++)
                    bf[nt] = *(const float2*)(Bq + nt * (8 * 36) + kk);
#pragma unroll
                for (int mt = 0; mt < 2; mt++)
#pragma unroll
                    for (int nt = 0; nt < 4; nt++)
                        mma_tf32(acc[mt][nt], af[mt][0], af[mt][1], bf[nt]);
            }
        }

#pragma unroll
        for (int mt = 0; mt < 2; mt++) {
            const int m0 = wm * 32 + mt * 16 + g;
#pragma unroll
            for (int nt = 0; nt < 4; nt++) {
                const int c0 = wn * 32 + nt * 8 + 2 * tg;
                float s0 = sc2[c0], s1 = sc2[c0 + 1];
                float t0 = bi2[c0], t1 = bi2[c0 + 1];
                feat[c0 * 64 + m0]           = fmaxf(acc[mt][nt][0] * s0 + t0, 0.f);
                feat[(c0 + 1) * 64 + m0]     = fmaxf(acc[mt][nt][1] * s1 + t1, 0.f);
                feat[c0 * 64 + m0 + 8]       = fmaxf(acc[mt][nt][2] * s0 + t0, 0.f);
                feat[(c0 + 1) * 64 + m0 + 8] = fmaxf(acc[mt][nt][3] * s1 + t1, 0.f);
            }
        }
        __syncthreads();

        for (int qq = u; qq < 1024; qq += 128) {
            int c = qq >> 4, blk = qq & 15;
            int bI = blk >> 2, bJ = blk & 3;
            int p00 = c * 64 + (bI * 2) * 8 + bJ * 2;
            float a = feat[p00], b = feat[p00 + 1];
            float cc = feat[p00 + 8], d = feat[p00 + 9];
            float v = (a - b - cc + d) * 0.5f;
            feat[p00]     = a  * v;
            feat[p00 + 1] = b  * v;
            feat[p00 + 8] = cc * v;
            feat[p00 + 9] = d  * v;
        }
        __syncthreads();

        if (u < 64) {
            float s = bav;
            for (int c = 0; c < 64; c++) s += feat[c * 64 + u] * was[c];
            attn[grp * 64 + u] = 1.f / (1.f + __expf(-s));
        }
        __syncthreads();

        float* fg = g_f + (size_t)n * 4096;
        for (int i = u; i < 4096; i += 128)
            fg[i] = to_tf32(feat[i] * attn[grp * 64 + (i & 63)]);
        __syncthreads();
    }
}

// ============================================================================
// tf32 GEMM, 128x128 tile, 128 threads, 4 warps of 64x64.
// A/B/C bound INTERNALLY to device globals (passing __device__ symbols as
// host-side kernel args is UB — that was the R4/R5 bug).
// MODE 0: g_h1 = tf32(relu(g_f @ g_wd1^T + bias)),      ldc=512
// MODE 1: out  = sigmoid(g_h1 @ g_wd2t^T + bias),       ldc=128
// ============================================================================
template<int KDIM, int MODE>
__global__ __launch_bounds__(128) void gemm_tf32_kernel(
    const float* __restrict__ bias, float* __restrict__ Cout)
{
    const float* A = (MODE == 0) ? g_f  : g_h1;
    const float* B = (MODE == 0) ? g_wd1 : g_wd2t;
    float*       C = (MODE == 0) ? g_h1 : Cout;
    const int  ldc = (MODE == 0) ? 512  : 128;

    extern __shared__ float smx[];
    float* As = smx;              // [2][128*24]
    float* Bs = smx + 6144;       // [2][128*24]

    const int t  = threadIdx.x;
    const int bn = blockIdx.x, bm = blockIdx.y;
    const int w  = t >> 5, lane = t & 31;
    const int wm = w >> 1, wn = w & 1;
    const int g  = lane >> 2, tg = lane & 3;

    const float* Ag = A + (size_t)(bm * 128 + t) * KDIM;
    const float* Bg = B + (size_t)(bn * 128 + t) * KDIM;
    const int sts = t * 24;

    float4 ar[4], br[4];
#pragma unroll
    for (int c = 0; c < 4; c++) {
        ar[c] = *(const float4*)(Ag + c * 4);
        br[c] = *(const float4*)(Bg + c * 4);
    }
#pragma unroll
    for (int c = 0; c < 4; c++) {
        *(float4*)&As[sts + c * 4] = ar[c];
        *(float4*)&Bs[sts + c * 4] = br[c];
    }
    __syncthreads();

    float acc[4][8][4];
#pragma unroll
    for (int mt = 0; mt < 4; mt++)
#pragma unroll
        for (int nt = 0; nt < 8; nt++)
#pragma unroll
            for (int i = 0; i < 4; i++) acc[mt][nt][i] = 0.f;

    const int NIT = KDIM / 16;
#pragma unroll 1
    for (int it = 0; it < NIT; it++) {
        const int cur = it & 1;
        if (it + 1 < NIT) {
#pragma unroll
            for (int c = 0; c < 4; c++) {
                ar[c] = *(const float4*)(Ag + (it + 1) * 16 + c * 4);
                br[c] = *(const float4*)(Bg + (it + 1) * 16 + c * 4);
            }
        }
        const float* Ab = As + cur * 3072;
        const float* Bb = Bs + cur * 3072;
#pragma unroll
        for (int kk = 0; kk < 16; kk += 8) {
            float2 af[4][2], bf[8];
#pragma unroll
            for (int mt = 0; mt < 4; mt++) {
                const int r = (wm * 64 + mt * 16 + g) * 24 + kk + 2 * tg;
                af[mt][0] = *(const float2*)&Ab[r];
                af[mt][1] = *(const float2*)&Ab[r + 192];
            }
#pragma unroll
            for (int nt = 0; nt < 8; nt++)
                bf[nt] = *(const float2*)&Bb[(wn * 64 + nt * 8 + g) * 24 + kk + 2 * tg];
#pragma unroll
            for (int mt = 0; mt < 4; mt++)
#pragma unroll
                for (int nt = 0; nt < 8; nt++)
                    mma_tf32(acc[mt][nt], af[mt][0], af[mt][1], bf[nt]);
        }
        if (it + 1 < NIT) {
            __syncthreads();
            const int o = (cur ^ 1) * 3072;
#pragma unroll
            for (int c = 0; c < 4; c++) {
                *(float4*)&As[o + sts + c * 4] = ar[c];
                *(float4*)&Bs[o + sts + c * 4] = br[c];
            }
            __syncthreads();
        }
    }

#pragma unroll
    for (int mt = 0; mt < 4; mt++) {
        const int m0 = bm * 128 + wm * 64 + mt * 16 + g;
#pragma unroll
        for (int nt = 0; nt < 8; nt++) {
            const int n0 = bn * 128 + wn * 64 + nt * 8 + 2 * tg;
            const float b0 = bias[n0], b1 = bias[n0 + 1];
            float2 r0, r1;
            if (MODE == 0) {
                r0.x = to_tf32(fmaxf(acc[mt][nt][0] + b0, 0.f));
                r0.y = to_tf32(fmaxf(acc[mt][nt][1] + b1, 0.f));
                r1.x = to_tf32(fmaxf(acc[mt][nt][2] + b0, 0.f));
                r1.y = to_tf32(fmaxf(acc[mt][nt][3] + b1, 0.f));
            } else {
                r0.x = 1.f / (1.f + __expf(-(acc[mt][nt][0] + b0)));
                r0.y = 1.f / (1.f + __expf(-(acc[mt][nt][1] + b1)));
                r1.x = 1.f / (1.f + __expf(-(acc[mt][nt][2] + b0)));
                r1.y = 1.f / (1.f + __expf(-(acc[mt][nt][3] + b1)));
            }
            *(float2*)&C[(size_t)m0 * ldc + n0]       = r0;
            *(float2*)&C[(size_t)(m0 + 8) * ldc + n0] = r1;
        }
    }
}

// ============================================================================
extern "C" void kernel_launch(void* const* d_in, const int* in_sizes, int n_in,
                              void* d_out, int out_size)
{
    const float* x   = (const float*)d_in[0];
    const float* w1  = (const float*)d_in[1];
    const float* b1  = (const float*)d_in[2];
    const float* g1  = (const float*)d_in[3];
    const float* be1 = (const float*)d_in[4];
    const float* m1  = (const float*)d_in[5];
    const float* v1  = (const float*)d_in[6];
    const float* w2  = (const float*)d_in[7];
    const float* b2  = (const float*)d_in[8];
    const float* g2  = (const float*)d_in[9];
    const float* be2 = (const float*)d_in[10];
    const float* m2  = (const float*)d_in[11];
    const float* v2  = (const float*)d_in[12];
    const float* wa  = (const float*)d_in[13];
    const float* ba  = (const float*)d_in[14];
    const float* wd1 = (const float*)d_in[15];
    const float* bd1 = (const float*)d_in[16];
    const float* wd2 = (const float*)d_in[17];
    const float* bd2 = (const float*)d_in[18];
    float* out = (float*)d_out;

    const int conv2_smem = C2_SMEM_FLOATS * 4;      // 210,304 B
    const int gemm_smem  = 12288 * 4;               // 49,152 B
    cudaFuncSetAttribute(conv2_mma_kernel,
                         cudaFuncAttributeMaxDynamicSharedMemorySize, conv2_smem);
    cudaFuncSetAttribute(gemm_tf32_kernel<4096, 0>,
                         cudaFuncAttributeMaxDynamicSharedMemorySize, gemm_smem);
    cudaFuncSetAttribute(gemm_tf32_kernel<512, 1>,
                         cudaFuncAttributeMaxDynamicSharedMemorySize, gemm_smem);

    cvt_wd1_kernel<<<2048, 256>>>(wd1);
    cvt_wd2_kernel<<<64, 256>>>(wd2);
    cvt_w2_kernel<<<72, 256>>>(w2);
    cvt_w1_kernel<<<15, 256>>>(w1);

    conv1_mma_kernel<<<BATCH, 128>>>(x, b1, g1, be1, m1, v1);
    conv2_mma_kernel<<<148, 256, conv2_smem>>>(b2, g2, be2, m2, v2, wa, ba);

    dim3 grid_fc1(4, 64);
    gemm_tf32_kernel<4096, 0><<<grid_fc1, 128, gemm_smem>>>(bd1, out);
    dim3 grid_fc2(1, 64);
    gemm_tf32_kernel<512, 1><<<grid_fc2, 128, gemm_smem>>>(bd2, out);
}

// round 7
// speedup vs baseline: 2.8174x; 1.0348x over previous
#include <cuda_runtime.h>
#include <math.h>
#include <stdint.h>

#define BN_EPS 1e-5f
#define BATCH 8192

// ---------------- scratch (device globals; no allocations allowed) ----------
__device__ float g_f[(size_t)BATCH * 64 * 8 * 8];     // flattened feat, tf32 (134MB)
__device__ float g_h1[(size_t)BATCH * 512];           // fc1 output, tf32 (16MB)
__device__ float g_wd1[(size_t)512 * 4096];           // tf32 wd1 (8MB)
__device__ float g_wd2t[(size_t)128 * 512];           // tf32 wd2
__device__ float g_wq[(size_t)9 * 64 * 36];           // conv2 W [q][oc][ic pad36] tf32
__device__ float g_w1q[(size_t)15 * 32 * 8];          // conv1 W [ic*5+ky][oc][kx pad8] tf32

__device__ __forceinline__ float to_tf32(float x) {
    uint32_t r;
    asm("cvt.rna.tf32.f32 %0, %1;" : "=r"(r) : "f"(x));
    return __uint_as_float(r);
}

__device__ __forceinline__ void mma_tf32(float* c, float2 a02, float2 a13, float2 b)
{
    asm volatile(
        "mma.sync.aligned.m16n8k8.row.col.f32.tf32.tf32.f32 "
        "{%0,%1,%2,%3}, {%4,%5,%6,%7}, {%8,%9}, {%0,%1,%2,%3};\n"
        : "+f"(c[0]), "+f"(c[1]), "+f"(c[2]), "+f"(c[3])
        : "r"(__float_as_uint(a02.x)), "r"(__float_as_uint(a13.x)),
          "r"(__float_as_uint(a02.y)), "r"(__float_as_uint(a13.y)),
          "r"(__float_as_uint(b.x)),   "r"(__float_as_uint(b.y)));
}

// ============================================================================
// Prep kernels
// ============================================================================
__global__ __launch_bounds__(256) void cvt_wd1_kernel(const float* __restrict__ wd1)
{
    int i = blockIdx.x * 256 + threadIdx.x;          // 524288 float4
    float4 v = ((const float4*)wd1)[i];
    v.x = to_tf32(v.x); v.y = to_tf32(v.y);
    v.z = to_tf32(v.z); v.w = to_tf32(v.w);
    ((float4*)g_wd1)[i] = v;
}

__global__ __launch_bounds__(256) void cvt_wd2_kernel(const float* __restrict__ wd2)
{
    int i = blockIdx.x * 256 + threadIdx.x;          // 16384 float4
    float4 v = ((const float4*)wd2)[i];
    v.x = to_tf32(v.x); v.y = to_tf32(v.y);
    v.z = to_tf32(v.z); v.w = to_tf32(v.w);
    ((float4*)g_wd2t)[i] = v;
}

__global__ __launch_bounds__(256) void cvt_w2_kernel(const float* __restrict__ w2)
{
    int i = blockIdx.x * 256 + threadIdx.x;   // 18432 = 64*32*9
    if (i >= 18432) return;
    int oc = i / 288;
    int rem = i % 288;
    int ic = rem / 9;
    int q  = rem % 9;
    g_wq[(q * 64 + oc) * 36 + ic] = to_tf32(w2[i]);
}

// w1 (oc,ic,5,5) -> g_w1q[(ic*5+ky)][oc][kx], kx padded to 8 with zeros
__global__ __launch_bounds__(256) void cvt_w1_kernel(const float* __restrict__ w1)
{
    int i = blockIdx.x * 256 + threadIdx.x;   // 15*32*8 = 3840
    if (i >= 3840) return;
    int tap = i >> 8;              // ic*5+ky
    int oc  = (i >> 3) & 31;
    int kx  = i & 7;
    int ic  = tap / 5, ky = tap % 5;
    float v = (kx < 5) ? w1[oc * 75 + ic * 25 + ky * 5 + kx] : 0.f;
    g_w1q[i] = to_tf32(v);
}

// ============================================================================
// FUSED conv1+conv2 kernel.  Persistent, 256 thr = 2 groups x 4 warps,
// one image per group per iteration.  conv1 mma -> BN/ReLU/tf32 -> hwc smem
// (padded conv2 input; no g_h round trip) -> conv2 mma -> BN/ReLU -> Haar ->
// attn sigmoid -> multiply -> g_f (tf32).
//
// smem float layout (total 56496 floats = 225,984 B):
//   wq     [20736]          conv2 weights [q][oc][ic pad36]
//   wb     [3840]           conv1 weights [tap][oc][kx pad8]
//   hwc    [2][11664]       conv2 input, padded 18x18 rows x 36  (borders 0)
//   xsfeat [2][4104]        conv1 input (3x36x38) ALIASED with feat (64x64)
//   attn   [2][64]
//   sc1[32] bi1[32] sc2[64] bi2[64] was[64]
// ============================================================================
#define FU_WQ     0
#define FU_WB     20736
#define FU_HWC    24576
#define FU_XSF    47904
#define FU_ATTN   56112
#define FU_SC1    56240
#define FU_BI1    56272
#define FU_SC2    56304
#define FU_BI2    56368
#define FU_WAS    56432
#define FU_TOTAL  56496

__global__ __launch_bounds__(256) void conv_fused_kernel(
    const float* __restrict__ x,
    const float* __restrict__ b1, const float* __restrict__ g1,
    const float* __restrict__ be1, const float* __restrict__ m1,
    const float* __restrict__ v1,
    const float* __restrict__ b2, const float* __restrict__ g2,
    const float* __restrict__ be2, const float* __restrict__ m2,
    const float* __restrict__ v2, const float* __restrict__ wa,
    const float* __restrict__ ba)
{
    extern __shared__ float sm[];
    float* wq   = sm + FU_WQ;
    float* wb   = sm + FU_WB;
    float* sc1  = sm + FU_SC1;
    float* bi1  = sm + FU_BI1;
    float* sc2  = sm + FU_SC2;
    float* bi2  = sm + FU_BI2;
    float* was  = sm + FU_WAS;

    const int t = threadIdx.x;

    for (int i = t; i < 20736; i += 256) wq[i] = g_wq[i];
    for (int i = t; i < 3840; i += 256) wb[i] = g_w1q[i];
    for (int i = t; i < 23328; i += 256) sm[FU_HWC + i] = 0.f;  // borders stay 0
    if (t < 32) {
        float s = g1[t] * rsqrtf(v1[t] + BN_EPS);
        sc1[t] = s;
        bi1[t] = be1[t] + (b1[t] - m1[t]) * s;
    }
    if (t < 64) {
        float s = g2[t] * rsqrtf(v2[t] + BN_EPS);
        sc2[t] = s;
        bi2[t] = be2[t] + (b2[t] - m2[t]) * s;
        was[t] = wa[t];
    }
    const float bav = ba[0];
    __syncthreads();

    const int grp  = t >> 7;
    const int u    = t & 127;
    const int w4   = u >> 5;
    const int lane = u & 31;
    const int g    = lane >> 2, tg = lane & 3;
    const int wm   = w4 >> 1, wn = w4 & 1;   // conv2 2x2 warp grid

    float* hwc  = sm + FU_HWC + grp * 11664;
    float* xs   = sm + FU_XSF + grp * 4104;   // aliased with feat
    float* feat = xs;
    float* attn = sm + FU_ATTN + grp * 64;

    // conv2 A base rows
    int baseA[2][2];
#pragma unroll
    for (int mt = 0; mt < 2; mt++)
#pragma unroll
        for (int r = 0; r < 2; r++) {
            int m = wm * 32 + mt * 16 + g + 8 * r;
            baseA[mt][r] = 36 * (m >> 3) + 2 * (m & 7);
        }

    for (int n0 = blockIdx.x * 2; n0 < BATCH; n0 += gridDim.x * 2) {
        const int n = n0 + grp;

        // ---- conv1 input: zero pad buffer, then fill interior ----
        for (int i = u; i < 4104; i += 128) xs[i] = 0.f;
        __syncthreads();
        const float* xg = x + (size_t)n * 3072;
        for (int i = u; i < 3072; i += 128) {
            int ic = i >> 10, rem = i & 1023;
            int iy = rem >> 5, ix = rem & 31;
            xs[ic * 1368 + (iy + 2) * 38 + ix + 2] = to_tf32(xg[i]);
        }
        __syncthreads();

        // ---- conv1 mma: C[256 pos][32 oc], k = kx(pad8), 15 taps ----
        {
            float acc[4][4][4];
#pragma unroll
            for (int mt = 0; mt < 4; mt++)
#pragma unroll
                for (int nt = 0; nt < 4; nt++)
#pragma unroll
                    for (int i = 0; i < 4; i++) acc[mt][nt][i] = 0.f;

#pragma unroll
            for (int tap = 0; tap < 15; tap++) {
                const int ic = tap / 5, ky = tap % 5;
                const float* Bp = wb + tap * 256 + g * 8 + 2 * tg;
                float2 bf[4];
#pragma unroll
                for (int nt = 0; nt < 4; nt++)
                    bf[nt] = *(const float2*)(Bp + nt * 64);
#pragma unroll
                for (int mt = 0; mt < 4; mt++) {
                    const int oy = (w4 << 2) + mt;
                    const float* Ap = xs + ic * 1368 + (2 * oy + ky) * 38 + 2 * tg;
                    float2 a0 = *(const float2*)(Ap + 2 * g);
                    float2 a1 = *(const float2*)(Ap + 2 * g + 16);
#pragma unroll
                    for (int nt = 0; nt < 4; nt++)
                        mma_tf32(acc[mt][nt], a0, a1, bf[nt]);
                }
            }
            __syncthreads();   // xs reads done before hwc interior overwrite? (hwc separate; sync orders vs prior iter g_f reads of feat alias)

            // BN + ReLU + tf32 -> hwc (padded conv2 input layout)
#pragma unroll
            for (int mt = 0; mt < 4; mt++) {
                const int oy = (w4 << 2) + mt;
#pragma unroll
                for (int nt = 0; nt < 4; nt++) {
                    const int oc = nt * 8 + 2 * tg;
                    const float s0 = sc1[oc], s1 = sc1[oc + 1];
                    const float t0 = bi1[oc], t1 = bi1[oc + 1];
                    float2 r0, r1;
                    r0.x = to_tf32(fmaxf(acc[mt][nt][0] * s0 + t0, 0.f));
                    r0.y = to_tf32(fmaxf(acc[mt][nt][1] * s1 + t1, 0.f));
                    r1.x = to_tf32(fmaxf(acc[mt][nt][2] * s0 + t0, 0.f));
                    r1.y = to_tf32(fmaxf(acc[mt][nt][3] * s1 + t1, 0.f));
                    *(float2*)&hwc[((oy + 1) * 18 + g + 1) * 36 + oc] = r0;
                    *(float2*)&hwc[((oy + 1) * 18 + g + 9) * 36 + oc] = r1;
                }
            }
        }
        __syncthreads();

        // ---- conv2 mma (proven R3) ----
        float acc[2][4][4];
#pragma unroll
        for (int mt = 0; mt < 2; mt++)
#pragma unroll
            for (int nt = 0; nt < 4; nt++)
#pragma unroll
                for (int i = 0; i < 4; i++) acc[mt][nt][i] = 0.f;

        for (int q = 0; q < 9; q++) {
            const int kh = q / 3, kw = q - kh * 3;
            const int dq = kh * 18 + kw;
            const float* A00 = hwc + (baseA[0][0] + dq) * 36 + 2 * tg;
            const float* A01 = hwc + (baseA[0][1] + dq) * 36 + 2 * tg;
            const float* A10 = hwc + (baseA[1][0] + dq) * 36 + 2 * tg;
            const float* A11 = hwc + (baseA[1][1] + dq) * 36 + 2 * tg;
            const float* Bq  = wq + (q * 64 + wn * 32 + g) * 36 + 2 * tg;
#pragma unroll
            for (int kk = 0; kk < 32; kk += 8) {
                float2 af[2][2], bf[4];
                af[0][0] = *(const float2*)(A00 + kk);
                af[0][1] = *(const float2*)(A01 + kk);
                af[1][0] = *(const float2*)(A10 + kk);
                af[1][1] = *(const float2*)(A11 + kk);
#pragma unroll
                for (int nt = 0; nt < 4; nt++)
                    bf[nt] = *(const float2*)(Bq + nt * (8 * 36) + kk);
#pragma unroll
                for (int mt = 0; mt < 2; mt++)
#pragma unroll
                    for (int nt = 0; nt < 4; nt++)
                        mma_tf32(acc[mt][nt], af[mt][0], af[mt][1], bf[nt]);
            }
        }
        __syncthreads();   // all xs (=feat alias) reads are long done; hwc reads done

        // BN + ReLU -> feat[oc][pos]
#pragma unroll
        for (int mt = 0; mt < 2; mt++) {
            const int m0 = wm * 32 + mt * 16 + g;
#pragma unroll
            for (int nt = 0; nt < 4; nt++) {
                const int c0 = wn * 32 + nt * 8 + 2 * tg;
                float s0 = sc2[c0], s1 = sc2[c0 + 1];
                float t0 = bi2[c0], t1 = bi2[c0 + 1];
                feat[c0 * 64 + m0]           = fmaxf(acc[mt][nt][0] * s0 + t0, 0.f);
                feat[(c0 + 1) * 64 + m0]     = fmaxf(acc[mt][nt][1] * s1 + t1, 0.f);
                feat[c0 * 64 + m0 + 8]       = fmaxf(acc[mt][nt][2] * s0 + t0, 0.f);
                feat[(c0 + 1) * 64 + m0 + 8] = fmaxf(acc[mt][nt][3] * s1 + t1, 0.f);
            }
        }
        __syncthreads();

        // Haar cD * upsample
        for (int qq = u; qq < 1024; qq += 128) {
            int c = qq >> 4, blk = qq & 15;
            int bI = blk >> 2, bJ = blk & 3;
            int p00 = c * 64 + (bI * 2) * 8 + bJ * 2;
            float a = feat[p00], b = feat[p00 + 1];
            float cc = feat[p00 + 8], d = feat[p00 + 9];
            float v = (a - b - cc + d) * 0.5f;
            feat[p00]     = a  * v;
            feat[p00 + 1] = b  * v;
            feat[p00 + 8] = cc * v;
            feat[p00 + 9] = d  * v;
        }
        __syncthreads();

        // 1x1 attn + sigmoid
        if (u < 64) {
            float s = bav;
            for (int c = 0; c < 64; c++) s += feat[c * 64 + u] * was[c];
            attn[u] = 1.f / (1.f + __expf(-s));
        }
        __syncthreads();

        // multiply & store tf32
        float* fg = g_f + (size_t)n * 4096;
        for (int i = u; i < 4096; i += 128)
            fg[i] = to_tf32(feat[i] * attn[i & 63]);
        __syncthreads();
    }
}

// ============================================================================
// tf32 GEMM, 128x128 tile, 128 threads, 4 warps of 64x64.
// A/B/C bound INTERNALLY to device globals.
// MODE 0: g_h1 = tf32(relu(g_f @ g_wd1^T + bias)),      ldc=512
// MODE 1: out  = sigmoid(g_h1 @ g_wd2t^T + bias),       ldc=128
// ============================================================================
template<int KDIM, int MODE>
__global__ __launch_bounds__(128) void gemm_tf32_kernel(
    const float* __restrict__ bias, float* __restrict__ Cout)
{
    const float* A = (MODE == 0) ? g_f  : g_h1;
    const float* B = (MODE == 0) ? g_wd1 : g_wd2t;
    float*       C = (MODE == 0) ? g_h1 : Cout;
    const int  ldc = (MODE == 0) ? 512  : 128;

    extern __shared__ float smx[];
    float* As = smx;              // [2][128*24]
    float* Bs = smx + 6144;       // [2][128*24]

    const int t  = threadIdx.x;
    const int bn = blockIdx.x, bm = blockIdx.y;
    const int w  = t >> 5, lane = t & 31;
    const int wm = w >> 1, wn = w & 1;
    const int g  = lane >> 2, tg = lane & 3;

    const float* Ag = A + (size_t)(bm * 128 + t) * KDIM;
    const float* Bg = B + (size_t)(bn * 128 + t) * KDIM;
    const int sts = t * 24;

    float4 ar[4], br[4];
#pragma unroll
    for (int c = 0; c < 4; c++) {
        ar[c] = *(const float4*)(Ag + c * 4);
        br[c] = *(const float4*)(Bg + c * 4);
    }
#pragma unroll
    for (int c = 0; c < 4; c++) {
        *(float4*)&As[sts + c * 4] = ar[c];
        *(float4*)&Bs[sts + c * 4] = br[c];
    }
    __syncthreads();

    float acc[4][8][4];
#pragma unroll
    for (int mt = 0; mt < 4; mt++)
#pragma unroll
        for (int nt = 0; nt < 8; nt++)
#pragma unroll
            for (int i = 0; i < 4; i++) acc[mt][nt][i] = 0.f;

    const int NIT = KDIM / 16;
#pragma unroll 1
    for (int it = 0; it < NIT; it++) {
        const int cur = it & 1;
        if (it + 1 < NIT) {
#pragma unroll
            for (int c = 0; c < 4; c++) {
                ar[c] = *(const float4*)(Ag + (it + 1) * 16 + c * 4);
                br[c] = *(const float4*)(Bg + (it + 1) * 16 + c * 4);
            }
        }
        const float* Ab = As + cur * 3072;
        const float* Bb = Bs + cur * 3072;
#pragma unroll
        for (int kk = 0; kk < 16; kk += 8) {
            float2 af[4][2], bf[8];
#pragma unroll
            for (int mt = 0; mt < 4; mt++) {
                const int r = (wm * 64 + mt * 16 + g) * 24 + kk + 2 * tg;
                af[mt][0] = *(const float2*)&Ab[r];
                af[mt][1] = *(const float2*)&Ab[r + 192];
            }
#pragma unroll
            for (int nt = 0; nt < 8; nt++)
                bf[nt] = *(const float2*)&Bb[(wn * 64 + nt * 8 + g) * 24 + kk + 2 * tg];
#pragma unroll
            for (int mt = 0; mt < 4; mt++)
#pragma unroll
                for (int nt = 0; nt < 8; nt++)
                    mma_tf32(acc[mt][nt], af[mt][0], af[mt][1], bf[nt]);
        }
        if (it + 1 < NIT) {
            __syncthreads();
            const int o = (cur ^ 1) * 3072;
#pragma unroll
            for (int c = 0; c < 4; c++) {
                *(float4*)&As[o + sts + c * 4] = ar[c];
                *(float4*)&Bs[o + sts + c * 4] = br[c];
            }
            __syncthreads();
        }
    }

#pragma unroll
    for (int mt = 0; mt < 4; mt++) {
        const int m0 = bm * 128 + wm * 64 + mt * 16 + g;
#pragma unroll
        for (int nt = 0; nt < 8; nt++) {
            const int n0 = bn * 128 + wn * 64 + nt * 8 + 2 * tg;
            const float b0 = bias[n0], b1 = bias[n0 + 1];
            float2 r0, r1;
            if (MODE == 0) {
                r0.x = to_tf32(fmaxf(acc[mt][nt][0] + b0, 0.f));
                r0.y = to_tf32(fmaxf(acc[mt][nt][1] + b1, 0.f));
                r1.x = to_tf32(fmaxf(acc[mt][nt][2] + b0, 0.f));
                r1.y = to_tf32(fmaxf(acc[mt][nt][3] + b1, 0.f));
            } else {
                r0.x = 1.f / (1.f + __expf(-(acc[mt][nt][0] + b0)));
                r0.y = 1.f / (1.f + __expf(-(acc[mt][nt][1] + b1)));
                r1.x = 1.f / (1.f + __expf(-(acc[mt][nt][2] + b0)));
                r1.y = 1.f / (1.f + __expf(-(acc[mt][nt][3] + b1)));
            }
            *(float2*)&C[(size_t)m0 * ldc + n0]       = r0;
            *(float2*)&C[(size_t)(m0 + 8) * ldc + n0] = r1;
        }
    }
}

// ============================================================================
extern "C" void kernel_launch(void* const* d_in, const int* in_sizes, int n_in,
                              void* d_out, int out_size)
{
    const float* x   = (const float*)d_in[0];
    const float* w1  = (const float*)d_in[1];
    const float* b1  = (const float*)d_in[2];
    const float* g1  = (const float*)d_in[3];
    const float* be1 = (const float*)d_in[4];
    const float* m1  = (const float*)d_in[5];
    const float* v1  = (const float*)d_in[6];
    const float* w2  = (const float*)d_in[7];
    const float* b2  = (const float*)d_in[8];
    const float* g2  = (const float*)d_in[9];
    const float* be2 = (const float*)d_in[10];
    const float* m2  = (const float*)d_in[11];
    const float* v2  = (const float*)d_in[12];
    const float* wa  = (const float*)d_in[13];
    const float* ba  = (const float*)d_in[14];
    const float* wd1 = (const float*)d_in[15];
    const float* bd1 = (const float*)d_in[16];
    const float* wd2 = (const float*)d_in[17];
    const float* bd2 = (const float*)d_in[18];
    float* out = (float*)d_out;

    const int fused_smem = FU_TOTAL * 4;            // 225,984 B
    const int gemm_smem  = 12288 * 4;               // 49,152 B
    cudaFuncSetAttribute(conv_fused_kernel,
                         cudaFuncAttributeMaxDynamicSharedMemorySize, fused_smem);
    cudaFuncSetAttribute(gemm_tf32_kernel<4096, 0>,
                         cudaFuncAttributeMaxDynamicSharedMemorySize, gemm_smem);
    cudaFuncSetAttribute(gemm_tf32_kernel<512, 1>,
                         cudaFuncAttributeMaxDynamicSharedMemorySize, gemm_smem);

    cvt_wd1_kernel<<<2048, 256>>>(wd1);
    cvt_wd2_kernel<<<64, 256>>>(wd2);
    cvt_w2_kernel<<<72, 256>>>(w2);
    cvt_w1_kernel<<<15, 256>>>(w1);

    conv_fused_kernel<<<148, 256, fused_smem>>>(x, b1, g1, be1, m1, v1,
                                                b2, g2, be2, m2, v2, wa, ba);

    dim3 grid_fc1(4, 64);
    gemm_tf32_kernel<4096, 0><<<grid_fc1, 128, gemm_smem>>>(bd1, out);
    dim3 grid_fc2(1, 64);
    gemm_tf32_kernel<512, 1><<<grid_fc2, 128, gemm_smem>>>(bd2, out);
}

// round 8
// speedup vs baseline: 3.7899x; 1.3451x over previous
#include <cuda_runtime.h>
#include <math.h>
#include <stdint.h>

#define BN_EPS 1e-5f
#define BATCH 8192

// ---------------- scratch (device globals; no allocations allowed) ----------
__device__ float g_f[(size_t)BATCH * 64 * 8 * 8];     // flattened feat, tf32 (134MB)
__device__ float g_h1[(size_t)BATCH * 512];           // fc1 output, tf32 (16MB)
__device__ float g_wd1[(size_t)512 * 4096];           // tf32 wd1 (8MB)
__device__ float g_wd2t[(size_t)128 * 512];           // tf32 wd2
__device__ float g_wq[(size_t)9 * 64 * 36];           // conv2 W [q][oc][ic pad36] tf32
__device__ float g_w1q[(size_t)15 * 32 * 8];          // conv1 W [ic*5+ky][oc][kx pad8] tf32

__device__ __forceinline__ float to_tf32(float x) {
    uint32_t r;
    asm("cvt.rna.tf32.f32 %0, %1;" : "=r"(r) : "f"(x));
    return __uint_as_float(r);
}

__device__ __forceinline__ void mma_tf32(float* c, float2 a02, float2 a13, float2 b)
{
    asm volatile(
        "mma.sync.aligned.m16n8k8.row.col.f32.tf32.tf32.f32 "
        "{%0,%1,%2,%3}, {%4,%5,%6,%7}, {%8,%9}, {%0,%1,%2,%3};\n"
        : "+f"(c[0]), "+f"(c[1]), "+f"(c[2]), "+f"(c[3])
        : "r"(__float_as_uint(a02.x)), "r"(__float_as_uint(a13.x)),
          "r"(__float_as_uint(a02.y)), "r"(__float_as_uint(a13.y)),
          "r"(__float_as_uint(b.x)),   "r"(__float_as_uint(b.y)));
}

__device__ __forceinline__ void cp_async16(uint32_t dst_smem, const void* src) {
    asm volatile("cp.async.cg.shared.global [%0], [%1], 16;\n"
                 :: "r"(dst_smem), "l"(src));
}
__device__ __forceinline__ void cp_commit() {
    asm volatile("cp.async.commit_group;\n" ::: "memory");
}
template<int N>
__device__ __forceinline__ void cp_wait() {
    asm volatile("cp.async.wait_group %0;\n" :: "n"(N) : "memory");
}

// ============================================================================
// Prep kernels
// ============================================================================
__global__ __launch_bounds__(256) void cvt_wd1_kernel(const float* __restrict__ wd1)
{
    int i = blockIdx.x * 256 + threadIdx.x;          // 524288 float4
    float4 v = ((const float4*)wd1)[i];
    v.x = to_tf32(v.x); v.y = to_tf32(v.y);
    v.z = to_tf32(v.z); v.w = to_tf32(v.w);
    ((float4*)g_wd1)[i] = v;
}

__global__ __launch_bounds__(256) void cvt_wd2_kernel(const float* __restrict__ wd2)
{
    int i = blockIdx.x * 256 + threadIdx.x;          // 16384 float4
    float4 v = ((const float4*)wd2)[i];
    v.x = to_tf32(v.x); v.y = to_tf32(v.y);
    v.z = to_tf32(v.z); v.w = to_tf32(v.w);
    ((float4*)g_wd2t)[i] = v;
}

__global__ __launch_bounds__(256) void cvt_w2_kernel(const float* __restrict__ w2)
{
    int i = blockIdx.x * 256 + threadIdx.x;   // 18432 = 64*32*9
    if (i >= 18432) return;
    int oc = i / 288;
    int rem = i % 288;
    int ic = rem / 9;
    int q  = rem % 9;
    g_wq[(q * 64 + oc) * 36 + ic] = to_tf32(w2[i]);
}

// w1 (oc,ic,5,5) -> g_w1q[(ic*5+ky)][oc][kx], kx padded to 8 with zeros
__global__ __launch_bounds__(256) void cvt_w1_kernel(const float* __restrict__ w1)
{
    int i = blockIdx.x * 256 + threadIdx.x;   // 15*32*8 = 3840
    if (i >= 3840) return;
    int tap = i >> 8;              // ic*5+ky
    int oc  = (i >> 3) & 31;
    int kx  = i & 7;
    int ic  = tap / 5, ky = tap % 5;
    float v = (kx < 5) ? w1[oc * 75 + ic * 25 + ky * 5 + kx] : 0.f;
    g_w1q[i] = to_tf32(v);
}

// ============================================================================
// FUSED conv1+conv2 kernel (PROVEN R7).  Persistent, 256 thr = 2 groups.
// ============================================================================
#define FU_WQ     0
#define FU_WB     20736
#define FU_HWC    24576
#define FU_XSF    47904
#define FU_ATTN   56112
#define FU_SC1    56240
#define FU_BI1    56272
#define FU_SC2    56304
#define FU_BI2    56368
#define FU_WAS    56432
#define FU_TOTAL  56496

__global__ __launch_bounds__(256) void conv_fused_kernel(
    const float* __restrict__ x,
    const float* __restrict__ b1, const float* __restrict__ g1,
    const float* __restrict__ be1, const float* __restrict__ m1,
    const float* __restrict__ v1,
    const float* __restrict__ b2, const float* __restrict__ g2,
    const float* __restrict__ be2, const float* __restrict__ m2,
    const float* __restrict__ v2, const float* __restrict__ wa,
    const float* __restrict__ ba)
{
    extern __shared__ float sm[];
    float* wq   = sm + FU_WQ;
    float* wb   = sm + FU_WB;
    float* sc1  = sm + FU_SC1;
    float* bi1  = sm + FU_BI1;
    float* sc2  = sm + FU_SC2;
    float* bi2  = sm + FU_BI2;
    float* was  = sm + FU_WAS;

    const int t = threadIdx.x;

    for (int i = t; i < 20736; i += 256) wq[i] = g_wq[i];
    for (int i = t; i < 3840; i += 256) wb[i] = g_w1q[i];
    for (int i = t; i < 23328; i += 256) sm[FU_HWC + i] = 0.f;  // borders stay 0
    if (t < 32) {
        float s = g1[t] * rsqrtf(v1[t] + BN_EPS);
        sc1[t] = s;
        bi1[t] = be1[t] + (b1[t] - m1[t]) * s;
    }
    if (t < 64) {
        float s = g2[t] * rsqrtf(v2[t] + BN_EPS);
        sc2[t] = s;
        bi2[t] = be2[t] + (b2[t] - m2[t]) * s;
        was[t] = wa[t];
    }
    const float bav = ba[0];
    __syncthreads();

    const int grp  = t >> 7;
    const int u    = t & 127;
    const int w4   = u >> 5;
    const int lane = u & 31;
    const int g    = lane >> 2, tg = lane & 3;
    const int wm   = w4 >> 1, wn = w4 & 1;

    float* hwc  = sm + FU_HWC + grp * 11664;
    float* xs   = sm + FU_XSF + grp * 4104;   // aliased with feat
    float* feat = xs;
    float* attn = sm + FU_ATTN + grp * 64;

    int baseA[2][2];
#pragma unroll
    for (int mt = 0; mt < 2; mt++)
#pragma unroll
        for (int r = 0; r < 2; r++) {
            int m = wm * 32 + mt * 16 + g + 8 * r;
            baseA[mt][r] = 36 * (m >> 3) + 2 * (m & 7);
        }

    for (int n0 = blockIdx.x * 2; n0 < BATCH; n0 += gridDim.x * 2) {
        const int n = n0 + grp;

        for (int i = u; i < 4104; i += 128) xs[i] = 0.f;
        __syncthreads();
        const float* xg = x + (size_t)n * 3072;
        for (int i = u; i < 3072; i += 128) {
            int ic = i >> 10, rem = i & 1023;
            int iy = rem >> 5, ix = rem & 31;
            xs[ic * 1368 + (iy + 2) * 38 + ix + 2] = to_tf32(xg[i]);
        }
        __syncthreads();

        // ---- conv1 mma ----
        {
            float acc[4][4][4];
#pragma unroll
            for (int mt = 0; mt < 4; mt++)
#pragma unroll
                for (int nt = 0; nt < 4; nt++)
#pragma unroll
                    for (int i = 0; i < 4; i++) acc[mt][nt][i] = 0.f;

#pragma unroll
            for (int tap = 0; tap < 15; tap++) {
                const int ic = tap / 5, ky = tap % 5;
                const float* Bp = wb + tap * 256 + g * 8 + 2 * tg;
                float2 bf[4];
#pragma unroll
                for (int nt = 0; nt < 4; nt++)
                    bf[nt] = *(const float2*)(Bp + nt * 64);
#pragma unroll
                for (int mt = 0; mt < 4; mt++) {
                    const int oy = (w4 << 2) + mt;
                    const float* Ap = xs + ic * 1368 + (2 * oy + ky) * 38 + 2 * tg;
                    float2 a0 = *(const float2*)(Ap + 2 * g);
                    float2 a1 = *(const float2*)(Ap + 2 * g + 16);
#pragma unroll
                    for (int nt = 0; nt < 4; nt++)
                        mma_tf32(acc[mt][nt], a0, a1, bf[nt]);
                }
            }
            __syncthreads();

#pragma unroll
            for (int mt = 0; mt < 4; mt++) {
                const int oy = (w4 << 2) + mt;
#pragma unroll
                for (int nt = 0; nt < 4; nt++) {
                    const int oc = nt * 8 + 2 * tg;
                    const float s0 = sc1[oc], s1 = sc1[oc + 1];
                    const float t0 = bi1[oc], t1 = bi1[oc + 1];
                    float2 r0, r1;
                    r0.x = to_tf32(fmaxf(acc[mt][nt][0] * s0 + t0, 0.f));
                    r0.y = to_tf32(fmaxf(acc[mt][nt][1] * s1 + t1, 0.f));
                    r1.x = to_tf32(fmaxf(acc[mt][nt][2] * s0 + t0, 0.f));
                    r1.y = to_tf32(fmaxf(acc[mt][nt][3] * s1 + t1, 0.f));
                    *(float2*)&hwc[((oy + 1) * 18 + g + 1) * 36 + oc] = r0;
                    *(float2*)&hwc[((oy + 1) * 18 + g + 9) * 36 + oc] = r1;
                }
            }
        }
        __syncthreads();

        // ---- conv2 mma ----
        float acc[2][4][4];
#pragma unroll
        for (int mt = 0; mt < 2; mt++)
#pragma unroll
            for (int nt = 0; nt < 4; nt++)
#pragma unroll
                for (int i = 0; i < 4; i++) acc[mt][nt][i] = 0.f;

        for (int q = 0; q < 9; q++) {
            const int kh = q / 3, kw = q - kh * 3;
            const int dq = kh * 18 + kw;
            const float* A00 = hwc + (baseA[0][0] + dq) * 36 + 2 * tg;
            const float* A01 = hwc + (baseA[0][1] + dq) * 36 + 2 * tg;
            const float* A10 = hwc + (baseA[1][0] + dq) * 36 + 2 * tg;
            const float* A11 = hwc + (baseA[1][1] + dq) * 36 + 2 * tg;
            const float* Bq  = wq + (q * 64 + wn * 32 + g) * 36 + 2 * tg;
#pragma unroll
            for (int kk = 0; kk < 32; kk += 8) {
                float2 af[2][2], bf[4];
                af[0][0] = *(const float2*)(A00 + kk);
                af[0][1] = *(const float2*)(A01 + kk);
                af[1][0] = *(const float2*)(A10 + kk);
                af[1][1] = *(const float2*)(A11 + kk);
#pragma unroll
                for (int nt = 0; nt < 4; nt++)
                    bf[nt] = *(const float2*)(Bq + nt * (8 * 36) + kk);
#pragma unroll
                for (int mt = 0; mt < 2; mt++)
#pragma unroll
                    for (int nt = 0; nt < 4; nt++)
                        mma_tf32(acc[mt][nt], af[mt][0], af[mt][1], bf[nt]);
            }
        }
        __syncthreads();

#pragma unroll
        for (int mt = 0; mt < 2; mt++) {
            const int m0 = wm * 32 + mt * 16 + g;
#pragma unroll
            for (int nt = 0; nt < 4; nt++) {
                const int c0 = wn * 32 + nt * 8 + 2 * tg;
                float s0 = sc2[c0], s1 = sc2[c0 + 1];
                float t0 = bi2[c0], t1 = bi2[c0 + 1];
                feat[c0 * 64 + m0]           = fmaxf(acc[mt][nt][0] * s0 + t0, 0.f);
                feat[(c0 + 1) * 64 + m0]     = fmaxf(acc[mt][nt][1] * s1 + t1, 0.f);
                feat[c0 * 64 + m0 + 8]       = fmaxf(acc[mt][nt][2] * s0 + t0, 0.f);
                feat[(c0 + 1) * 64 + m0 + 8] = fmaxf(acc[mt][nt][3] * s1 + t1, 0.f);
            }
        }
        __syncthreads();

        for (int qq = u; qq < 1024; qq += 128) {
            int c = qq >> 4, blk = qq & 15;
            int bI = blk >> 2, bJ = blk & 3;
            int p00 = c * 64 + (bI * 2) * 8 + bJ * 2;
            float a = feat[p00], b = feat[p00 + 1];
            float cc = feat[p00 + 8], d = feat[p00 + 9];
            float v = (a - b - cc + d) * 0.5f;
            feat[p00]     = a  * v;
            feat[p00 + 1] = b  * v;
            feat[p00 + 8] = cc * v;
            feat[p00 + 9] = d  * v;
        }
        __syncthreads();

        if (u < 64) {
            float s = bav;
            for (int c = 0; c < 64; c++) s += feat[c * 64 + u] * was[c];
            attn[u] = 1.f / (1.f + __expf(-s));
        }
        __syncthreads();

        float* fg = g_f + (size_t)n * 4096;
        for (int i = u; i < 4096; i += 128)
            fg[i] = to_tf32(feat[i] * attn[i & 63]);
        __syncthreads();
    }
}

// ============================================================================
// tf32 GEMM v2: 128x128 tile, 256 threads (8 warps, warp tile 32x64),
// cp.async 3-stage pipeline, one __syncthreads per k16 stage.
// A/B/C bound internally.
// MODE 0: g_h1 = tf32(relu(g_f @ g_wd1^T + bias)),   ldc=512
// MODE 1: out  = sigmoid(g_h1 @ g_wd2t^T + bias),    ldc=128
// ============================================================================
#define GSTAGE 3
#define GSTRIDE 3072            // 128 rows * 24 floats per stage

template<int KDIM, int MODE>
__global__ __launch_bounds__(256, 2) void gemm_tf32_kernel(
    const float* __restrict__ bias, float* __restrict__ Cout)
{
    const float* A = (MODE == 0) ? g_f  : g_h1;
    const float* B = (MODE == 0) ? g_wd1 : g_wd2t;
    float*       C = (MODE == 0) ? g_h1 : Cout;
    const int  ldc = (MODE == 0) ? 512  : 128;

    extern __shared__ float smx[];
    float* As = smx;                        // [3][3072]
    float* Bs = smx + GSTAGE * GSTRIDE;     // [3][3072]
    const uint32_t AsU = (uint32_t)__cvta_generic_to_shared(As);
    const uint32_t BsU = (uint32_t)__cvta_generic_to_shared(Bs);

    const int t  = threadIdx.x;
    const int bn = blockIdx.x, bm = blockIdx.y;
    const int w  = t >> 5, lane = t & 31;
    const int wm = w >> 1, wn = w & 1;      // 4 x 2 warp grid, warp tile 32x64
    const int g  = lane >> 2, tg = lane & 3;

    // per-thread cp.async slots: 2 float4 per matrix per stage
    int rowv[2], kov[2];
#pragma unroll
    for (int j = 0; j < 2; j++) {
        int v = t + 256 * j;
        rowv[j] = v >> 2;
        kov[j]  = (v & 3) * 4;
    }
    const float* PA[2];
    const float* PB[2];
    uint32_t DA[2], DB[2];
#pragma unroll
    for (int j = 0; j < 2; j++) {
        PA[j] = A + (size_t)(bm * 128 + rowv[j]) * KDIM + kov[j];
        PB[j] = B + (size_t)(bn * 128 + rowv[j]) * KDIM + kov[j];
        DA[j] = AsU + (rowv[j] * 24 + kov[j]) * 4;
        DB[j] = BsU + (rowv[j] * 24 + kov[j]) * 4;
    }

    const int NIT = KDIM / 16;

    // prologue: stages 0 and 1
#pragma unroll
    for (int s = 0; s < 2; s++) {
#pragma unroll
        for (int j = 0; j < 2; j++) {
            cp_async16(DA[j] + s * (GSTRIDE * 4), PA[j] + s * 16);
            cp_async16(DB[j] + s * (GSTRIDE * 4), PB[j] + s * 16);
        }
        cp_commit();
    }

    float acc[2][8][4];
#pragma unroll
    for (int mt = 0; mt < 2; mt++)
#pragma unroll
        for (int nt = 0; nt < 8; nt++)
#pragma unroll
            for (int i = 0; i < 4; i++) acc[mt][nt][i] = 0.f;

    const int ar0 = (wm * 32 + g) * 24 + 2 * tg;       // +mt*384, +192 row+8
    const int br0 = (wn * 64 + g) * 24 + 2 * tg;       // +nt*192

#pragma unroll 1
    for (int it = 0; it < NIT; it++) {
        const int s = it % GSTAGE;
        if (it + 2 < NIT) cp_wait<1>(); else cp_wait<0>();
        __syncthreads();

        if (it + 2 < NIT) {
            const int sn = (it + 2) % GSTAGE;
#pragma unroll
            for (int j = 0; j < 2; j++) {
                cp_async16(DA[j] + sn * (GSTRIDE * 4), PA[j] + (it + 2) * 16);
                cp_async16(DB[j] + sn * (GSTRIDE * 4), PB[j] + (it + 2) * 16);
            }
            cp_commit();
        }

        const float* Ab = As + s * GSTRIDE;
        const float* Bb = Bs + s * GSTRIDE;
#pragma unroll
        for (int kk = 0; kk < 16; kk += 8) {
            float2 af[2][2], bf[8];
#pragma unroll
            for (int mt = 0; mt < 2; mt++) {
                af[mt][0] = *(const float2*)&Ab[ar0 + mt * 384 + kk];
                af[mt][1] = *(const float2*)&Ab[ar0 + mt * 384 + 192 + kk];
            }
#pragma unroll
            for (int nt = 0; nt < 8; nt++)
                bf[nt] = *(const float2*)&Bb[br0 + nt * 192 + kk];
#pragma unroll
            for (int mt = 0; mt < 2; mt++)
#pragma unroll
                for (int nt = 0; nt < 8; nt++)
                    mma_tf32(acc[mt][nt], af[mt][0], af[mt][1], bf[nt]);
        }
        __syncthreads();
    }

#pragma unroll
    for (int mt = 0; mt < 2; mt++) {
        const int m0 = bm * 128 + wm * 32 + mt * 16 + g;
#pragma unroll
        for (int nt = 0; nt < 8; nt++) {
            const int n0 = bn * 128 + wn * 64 + nt * 8 + 2 * tg;
            const float b0 = bias[n0], b1 = bias[n0 + 1];
            float2 r0, r1;
            if (MODE == 0) {
                r0.x = to_tf32(fmaxf(acc[mt][nt][0] + b0, 0.f));
                r0.y = to_tf32(fmaxf(acc[mt][nt][1] + b1, 0.f));
                r1.x = to_tf32(fmaxf(acc[mt][nt][2] + b0, 0.f));
                r1.y = to_tf32(fmaxf(acc[mt][nt][3] + b1, 0.f));
            } else {
                r0.x = 1.f / (1.f + __expf(-(acc[mt][nt][0] + b0)));
                r0.y = 1.f / (1.f + __expf(-(acc[mt][nt][1] + b1)));
                r1.x = 1.f / (1.f + __expf(-(acc[mt][nt][2] + b0)));
                r1.y = 1.f / (1.f + __expf(-(acc[mt][nt][3] + b1)));
            }
            *(float2*)&C[(size_t)m0 * ldc + n0]       = r0;
            *(float2*)&C[(size_t)(m0 + 8) * ldc + n0] = r1;
        }
    }
}

// ============================================================================
extern "C" void kernel_launch(void* const* d_in, const int* in_sizes, int n_in,
                              void* d_out, int out_size)
{
    const float* x   = (const float*)d_in[0];
    const float* w1  = (const float*)d_in[1];
    const float* b1  = (const float*)d_in[2];
    const float* g1  = (const float*)d_in[3];
    const float* be1 = (const float*)d_in[4];
    const float* m1  = (const float*)d_in[5];
    const float* v1  = (const float*)d_in[6];
    const float* w2  = (const float*)d_in[7];
    const float* b2  = (const float*)d_in[8];
    const float* g2  = (const float*)d_in[9];
    const float* be2 = (const float*)d_in[10];
    const float* m2  = (const float*)d_in[11];
    const float* v2  = (const float*)d_in[12];
    const float* wa  = (const float*)d_in[13];
    const float* ba  = (const float*)d_in[14];
    const float* wd1 = (const float*)d_in[15];
    const float* bd1 = (const float*)d_in[16];
    const float* wd2 = (const float*)d_in[17];
    const float* bd2 = (const float*)d_in[18];
    float* out = (float*)d_out;

    const int fused_smem = FU_TOTAL * 4;                    // 225,984 B
    const int gemm_smem  = GSTAGE * GSTRIDE * 2 * 4;        // 73,728 B
    cudaFuncSetAttribute(conv_fused_kernel,
                         cudaFuncAttributeMaxDynamicSharedMemorySize, fused_smem);
    cudaFuncSetAttribute(gemm_tf32_kernel<4096, 0>,
                         cudaFuncAttributeMaxDynamicSharedMemorySize, gemm_smem);
    cudaFuncSetAttribute(gemm_tf32_kernel<512, 1>,
                         cudaFuncAttributeMaxDynamicSharedMemorySize, gemm_smem);

    cvt_wd1_kernel<<<2048, 256>>>(wd1);
    cvt_wd2_kernel<<<64, 256>>>(wd2);
    cvt_w2_kernel<<<72, 256>>>(w2);
    cvt_w1_kernel<<<15, 256>>>(w1);

    conv_fused_kernel<<<148, 256, fused_smem>>>(x, b1, g1, be1, m1, v1,
                                                b2, g2, be2, m2, v2, wa, ba);

    dim3 grid_fc1(4, 64);
    gemm_tf32_kernel<4096, 0><<<grid_fc1, 256, gemm_smem>>>(bd1, out);
    dim3 grid_fc2(1, 64);
    gemm_tf32_kernel<512, 1><<<grid_fc2, 256, gemm_smem>>>(bd2, out);
}

// round 9
// speedup vs baseline: 4.2073x; 1.1101x over previous
#include <cuda_runtime.h>
#include <math.h>
#include <stdint.h>

#define BN_EPS 1e-5f
#define BATCH 8192

// ---------------- scratch (device globals; no allocations allowed) ----------
__device__ float g_f[(size_t)BATCH * 64 * 8 * 8];     // flattened feat, tf32 (134MB)
__device__ float g_h1[(size_t)BATCH * 512];           // fc1 output, tf32 (16MB)
__device__ float g_wd1[(size_t)512 * 4096];           // tf32 wd1 (8MB)
__device__ float g_wd2t[(size_t)128 * 512];           // tf32 wd2
__device__ float g_wq[(size_t)9 * 64 * 36];           // conv2 W [q][oc][ic pad36] tf32
__device__ float g_w1q[(size_t)15 * 32 * 8];          // conv1 W [ic*5+ky][oc][kx pad8] tf32

__device__ __forceinline__ float to_tf32(float x) {
    uint32_t r;
    asm("cvt.rna.tf32.f32 %0, %1;" : "=r"(r) : "f"(x));
    return __uint_as_float(r);
}

__device__ __forceinline__ void mma_tf32(float* c, float2 a02, float2 a13, float2 b)
{
    asm volatile(
        "mma.sync.aligned.m16n8k8.row.col.f32.tf32.tf32.f32 "
        "{%0,%1,%2,%3}, {%4,%5,%6,%7}, {%8,%9}, {%0,%1,%2,%3};\n"
        : "+f"(c[0]), "+f"(c[1]), "+f"(c[2]), "+f"(c[3])
        : "r"(__float_as_uint(a02.x)), "r"(__float_as_uint(a13.x)),
          "r"(__float_as_uint(a02.y)), "r"(__float_as_uint(a13.y)),
          "r"(__float_as_uint(b.x)),   "r"(__float_as_uint(b.y)));
}

__device__ __forceinline__ void cp_async16(uint32_t dst_smem, const void* src) {
    asm volatile("cp.async.cg.shared.global [%0], [%1], 16;\n"
                 :: "r"(dst_smem), "l"(src));
}
__device__ __forceinline__ void cp_async8(uint32_t dst_smem, const void* src) {
    asm volatile("cp.async.ca.shared.global [%0], [%1], 8;\n"
                 :: "r"(dst_smem), "l"(src));
}
__device__ __forceinline__ void cp_commit() {
    asm volatile("cp.async.commit_group;\n" ::: "memory");
}
template<int N>
__device__ __forceinline__ void cp_wait() {
    asm volatile("cp.async.wait_group %0;\n" :: "n"(N) : "memory");
}

#define BARG(grp) asm volatile("bar.sync %0, 128;" :: "r"((grp) + 1) : "memory")

// ============================================================================
// Prep kernels
// ============================================================================
__global__ __launch_bounds__(256) void cvt_wd1_kernel(const float* __restrict__ wd1)
{
    int i = blockIdx.x * 256 + threadIdx.x;          // 524288 float4
    float4 v = ((const float4*)wd1)[i];
    v.x = to_tf32(v.x); v.y = to_tf32(v.y);
    v.z = to_tf32(v.z); v.w = to_tf32(v.w);
    ((float4*)g_wd1)[i] = v;
}

__global__ __launch_bounds__(256) void cvt_wd2_kernel(const float* __restrict__ wd2)
{
    int i = blockIdx.x * 256 + threadIdx.x;          // 16384 float4
    float4 v = ((const float4*)wd2)[i];
    v.x = to_tf32(v.x); v.y = to_tf32(v.y);
    v.z = to_tf32(v.z); v.w = to_tf32(v.w);
    ((float4*)g_wd2t)[i] = v;
}

__global__ __launch_bounds__(256) void cvt_w2_kernel(const float* __restrict__ w2)
{
    int i = blockIdx.x * 256 + threadIdx.x;   // 18432 = 64*32*9
    if (i >= 18432) return;
    int oc = i / 288;
    int rem = i % 288;
    int ic = rem / 9;
    int q  = rem % 9;
    g_wq[(q * 64 + oc) * 36 + ic] = to_tf32(w2[i]);
}

// w1 (oc,ic,5,5) -> g_w1q[(ic*5+ky)][oc][kx], kx padded to 8 with zeros
__global__ __launch_bounds__(256) void cvt_w1_kernel(const float* __restrict__ w1)
{
    int i = blockIdx.x * 256 + threadIdx.x;   // 15*32*8 = 3840
    if (i >= 3840) return;
    int tap = i >> 8;              // ic*5+ky
    int oc  = (i >> 3) & 31;
    int kx  = i & 7;
    int ic  = tap / 5, ky = tap % 5;
    float v = (kx < 5) ? w1[oc * 75 + ic * 25 + ky * 5 + kx] : 0.f;
    g_w1q[i] = to_tf32(v);
}

// ============================================================================
// FUSED conv1+conv2 v2.  Persistent, 256 thr = 2 independent 128-thr groups
// (named barriers).  xs is a dedicated persistent buffer (borders zeroed once)
// filled by cp.async prefetch of the NEXT image during the epilogue phase;
// feat aliases hwc[0:4096) (its border cells re-zeroed each iteration).
//
// smem float layout (56496 floats = 225,984 B):
//   wq[20736] wb[3840] hwc[2][11664] xs[2][4104] attn[2][64]
//   sc1[32] bi1[32] sc2[64] bi2[64] was[64]
// ============================================================================
#define FU_WQ     0
#define FU_WB     20736
#define FU_HWC    24576
#define FU_XS     47904
#define FU_ATTN   56112
#define FU_SC1    56240
#define FU_BI1    56272
#define FU_SC2    56304
#define FU_BI2    56368
#define FU_WAS    56432
#define FU_TOTAL  56496

__global__ __launch_bounds__(256) void conv_fused_kernel(
    const float* __restrict__ x,
    const float* __restrict__ b1, const float* __restrict__ g1,
    const float* __restrict__ be1, const float* __restrict__ m1,
    const float* __restrict__ v1,
    const float* __restrict__ b2, const float* __restrict__ g2,
    const float* __restrict__ be2, const float* __restrict__ m2,
    const float* __restrict__ v2, const float* __restrict__ wa,
    const float* __restrict__ ba)
{
    extern __shared__ float sm[];
    float* wq   = sm + FU_WQ;
    float* wb   = sm + FU_WB;
    float* sc1  = sm + FU_SC1;
    float* bi1  = sm + FU_BI1;
    float* sc2  = sm + FU_SC2;
    float* bi2  = sm + FU_BI2;
    float* was  = sm + FU_WAS;

    const int t = threadIdx.x;

    for (int i = t; i < 20736; i += 256) wq[i] = g_wq[i];
    for (int i = t; i < 3840; i += 256) wb[i] = g_w1q[i];
    for (int i = t; i < 23328; i += 256) sm[FU_HWC + i] = 0.f;
    for (int i = t; i < 8208; i += 256) sm[FU_XS + i] = 0.f;   // xs borders persist
    if (t < 32) {
        float s = g1[t] * rsqrtf(v1[t] + BN_EPS);
        sc1[t] = s;
        bi1[t] = be1[t] + (b1[t] - m1[t]) * s;
    }
    if (t < 64) {
        float s = g2[t] * rsqrtf(v2[t] + BN_EPS);
        sc2[t] = s;
        bi2[t] = be2[t] + (b2[t] - m2[t]) * s;
        was[t] = wa[t];
    }
    const float bav = ba[0];
    __syncthreads();

    const int grp  = t >> 7;
    const int u    = t & 127;
    const int w4   = u >> 5;
    const int lane = u & 31;
    const int g    = lane >> 2, tg = lane & 3;
    const int wm   = w4 >> 1, wn = w4 & 1;

    float* hwc  = sm + FU_HWC + grp * 11664;
    float* feat = hwc;                          // aliases hwc[0:4096)
    float* xs   = sm + FU_XS + grp * 4104;
    float* attn = sm + FU_ATTN + grp * 64;
    const uint32_t xsU = (uint32_t)__cvta_generic_to_shared(xs);

    int baseA[2][2];
#pragma unroll
    for (int mt = 0; mt < 2; mt++)
#pragma unroll
        for (int r = 0; r < 2; r++) {
            int m = wm * 32 + mt * 16 + g + 8 * r;
            baseA[mt][r] = 36 * (m >> 3) + 2 * (m & 7);
        }

    const int stride = gridDim.x * 2;
    const int n0 = blockIdx.x * 2 + grp;

    // prologue prefetch: image n0 -> xs (raw f32, 8B chunks)
    if (n0 < BATCH) {
        const float* src = x + (size_t)n0 * 3072;
#pragma unroll
        for (int j = 0; j < 12; j++) {
            int i2 = 2 * (u + 128 * j);
            int ic = i2 >> 10, rem = i2 & 1023, iy = rem >> 5, ix = rem & 31;
            cp_async8(xsU + (ic * 1368 + (iy + 2) * 38 + ix + 2) * 4, src + i2);
        }
        cp_commit();
    }

    for (int n = n0; n < BATCH; n += stride) {
        // ---- publish prefetched x: in-place RNA cvt of own chunks ----
        cp_wait<0>();
#pragma unroll
        for (int j = 0; j < 12; j++) {
            int i2 = 2 * (u + 128 * j);
            int ic = i2 >> 10, rem = i2 & 1023, iy = rem >> 5, ix = rem & 31;
            float2* p = (float2*)(xs + ic * 1368 + (iy + 2) * 38 + ix + 2);
            float2 v = *p;
            v.x = to_tf32(v.x); v.y = to_tf32(v.y);
            *p = v;
        }
        BARG(grp);

        // ---- conv1 mma ----
        {
            float acc[4][4][4];
#pragma unroll
            for (int mt = 0; mt < 4; mt++)
#pragma unroll
                for (int nt = 0; nt < 4; nt++)
#pragma unroll
                    for (int i = 0; i < 4; i++) acc[mt][nt][i] = 0.f;

#pragma unroll
            for (int tap = 0; tap < 15; tap++) {
                const int ic = tap / 5, ky = tap % 5;
                const float* Bp = wb + tap * 256 + g * 8 + 2 * tg;
                float2 bf[4];
#pragma unroll
                for (int nt = 0; nt < 4; nt++)
                    bf[nt] = *(const float2*)(Bp + nt * 64);
#pragma unroll
                for (int mt = 0; mt < 4; mt++) {
                    const int oy = (w4 << 2) + mt;
                    const float* Ap = xs + ic * 1368 + (2 * oy + ky) * 38 + 2 * tg;
                    float2 a0 = *(const float2*)(Ap + 2 * g);
                    float2 a1 = *(const float2*)(Ap + 2 * g + 16);
#pragma unroll
                    for (int nt = 0; nt < 4; nt++)
                        mma_tf32(acc[mt][nt], a0, a1, bf[nt]);
                }
            }
            BARG(grp);   // xs reads done -> safe to prefetch into xs

            // ---- epilogue phase: hwc interior + feat-region border zero +
            //      prefetch next image into xs ----
#pragma unroll
            for (int mt = 0; mt < 4; mt++) {
                const int oy = (w4 << 2) + mt;
#pragma unroll
                for (int nt = 0; nt < 4; nt++) {
                    const int oc = nt * 8 + 2 * tg;
                    const float s0 = sc1[oc], s1 = sc1[oc + 1];
                    const float t0 = bi1[oc], t1 = bi1[oc + 1];
                    float2 r0, r1;
                    r0.x = to_tf32(fmaxf(acc[mt][nt][0] * s0 + t0, 0.f));
                    r0.y = to_tf32(fmaxf(acc[mt][nt][1] * s1 + t1, 0.f));
                    r1.x = to_tf32(fmaxf(acc[mt][nt][2] * s0 + t0, 0.f));
                    r1.y = to_tf32(fmaxf(acc[mt][nt][3] * s1 + t1, 0.f));
                    *(float2*)&hwc[((oy + 1) * 18 + g + 1) * 36 + oc] = r0;
                    *(float2*)&hwc[((oy + 1) * 18 + g + 9) * 36 + oc] = r1;
                }
            }
            // re-zero border cells inside feat region [0, 4096): 29 positions
            for (int jj = u; jj < 1044; jj += 128) {
                int j = jj / 36, ic = jj % 36;
                int pos;
                if (j < 18)      pos = j;
                else if (j < 28) { int r = j - 18; pos = (r / 2 + 1) * 18 + (r & 1) * 17; }
                else             pos = 108;
                hwc[pos * 36 + ic] = 0.f;
            }
            // prefetch next image's x (raw) into xs
            const int n_next = n + stride;
            if (n_next < BATCH) {
                const float* src = x + (size_t)n_next * 3072;
#pragma unroll
                for (int j = 0; j < 12; j++) {
                    int i2 = 2 * (u + 128 * j);
                    int ic = i2 >> 10, rem = i2 & 1023, iy = rem >> 5, ix = rem & 31;
                    cp_async8(xsU + (ic * 1368 + (iy + 2) * 38 + ix + 2) * 4, src + i2);
                }
                cp_commit();
            }
        }
        BARG(grp);   // hwc ready

        // ---- conv2 mma ----
        float acc[2][4][4];
#pragma unroll
        for (int mt = 0; mt < 2; mt++)
#pragma unroll
            for (int nt = 0; nt < 4; nt++)
#pragma unroll
                for (int i = 0; i < 4; i++) acc[mt][nt][i] = 0.f;

        for (int q = 0; q < 9; q++) {
            const int kh = q / 3, kw = q - kh * 3;
            const int dq = kh * 18 + kw;
            const float* A00 = hwc + (baseA[0][0] + dq) * 36 + 2 * tg;
            const float* A01 = hwc + (baseA[0][1] + dq) * 36 + 2 * tg;
            const float* A10 = hwc + (baseA[1][0] + dq) * 36 + 2 * tg;
            const float* A11 = hwc + (baseA[1][1] + dq) * 36 + 2 * tg;
            const float* Bq  = wq + (q * 64 + wn * 32 + g) * 36 + 2 * tg;
#pragma unroll
            for (int kk = 0; kk < 32; kk += 8) {
                float2 af[2][2], bf[4];
                af[0][0] = *(const float2*)(A00 + kk);
                af[0][1] = *(const float2*)(A01 + kk);
                af[1][0] = *(const float2*)(A10 + kk);
                af[1][1] = *(const float2*)(A11 + kk);
#pragma unroll
                for (int nt = 0; nt < 4; nt++)
                    bf[nt] = *(const float2*)(Bq + nt * (8 * 36) + kk);
#pragma unroll
                for (int mt = 0; mt < 2; mt++)
#pragma unroll
                    for (int nt = 0; nt < 4; nt++)
                        mma_tf32(acc[mt][nt], af[mt][0], af[mt][1], bf[nt]);
            }
        }
        BARG(grp);   // hwc reads done (incl. feat region)

        // BN + ReLU -> feat[oc][pos]  (feat aliases hwc[0:4096))
#pragma unroll
        for (int mt = 0; mt < 2; mt++) {
            const int m0 = wm * 32 + mt * 16 + g;
#pragma unroll
            for (int nt = 0; nt < 4; nt++) {
                const int c0 = wn * 32 + nt * 8 + 2 * tg;
                float s0 = sc2[c0], s1 = sc2[c0 + 1];
                float t0 = bi2[c0], t1 = bi2[c0 + 1];
                feat[c0 * 64 + m0]           = fmaxf(acc[mt][nt][0] * s0 + t0, 0.f);
                feat[(c0 + 1) * 64 + m0]     = fmaxf(acc[mt][nt][1] * s1 + t1, 0.f);
                feat[c0 * 64 + m0 + 8]       = fmaxf(acc[mt][nt][2] * s0 + t0, 0.f);
                feat[(c0 + 1) * 64 + m0 + 8] = fmaxf(acc[mt][nt][3] * s1 + t1, 0.f);
            }
        }
        BARG(grp);

        // Haar cD * upsample
        for (int qq = u; qq < 1024; qq += 128) {
            int c = qq >> 4, blk = qq & 15;
            int bI = blk >> 2, bJ = blk & 3;
            int p00 = c * 64 + (bI * 2) * 8 + bJ * 2;
            float a = feat[p00], b = feat[p00 + 1];
            float cc = feat[p00 + 8], d = feat[p00 + 9];
            float v = (a - b - cc + d) * 0.5f;
            feat[p00]     = a  * v;
            feat[p00 + 1] = b  * v;
            feat[p00 + 8] = cc * v;
            feat[p00 + 9] = d  * v;
        }
        BARG(grp);

        // 1x1 attn + sigmoid
        if (u < 64) {
            float s = bav;
            for (int c = 0; c < 64; c++) s += feat[c * 64 + u] * was[c];
            attn[u] = 1.f / (1.f + __expf(-s));
        }
        BARG(grp);

        // multiply & store tf32
        float* fg = g_f + (size_t)n * 4096;
        for (int i = u; i < 4096; i += 128)
            fg[i] = to_tf32(feat[i] * attn[i & 63]);
        BARG(grp);   // feat reads done; next iter may overwrite hwc
    }
}

// ============================================================================
// tf32 GEMM v3: 128x128 tile, 256 threads (8 warps, warp tile 32x64),
// cp.async 4-stage pipeline, distance-3 prefetch, ONE barrier per k16.
// MODE 0: g_h1 = tf32(relu(g_f @ g_wd1^T + bias)),   ldc=512
// MODE 1: out  = sigmoid(g_h1 @ g_wd2t^T + bias),    ldc=128
// ============================================================================
#define GSTAGE 4
#define GSTRIDE 3072            // 128 rows * 24 floats per stage

template<int KDIM, int MODE>
__global__ __launch_bounds__(256, 2) void gemm_tf32_kernel(
    const float* __restrict__ bias, float* __restrict__ Cout)
{
    const float* A = (MODE == 0) ? g_f  : g_h1;
    const float* B = (MODE == 0) ? g_wd1 : g_wd2t;
    float*       C = (MODE == 0) ? g_h1 : Cout;
    const int  ldc = (MODE == 0) ? 512  : 128;

    extern __shared__ float smx[];
    float* As = smx;                        // [4][3072]
    float* Bs = smx + GSTAGE * GSTRIDE;     // [4][3072]
    const uint32_t AsU = (uint32_t)__cvta_generic_to_shared(As);
    const uint32_t BsU = (uint32_t)__cvta_generic_to_shared(Bs);

    const int t  = threadIdx.x;
    const int bn = blockIdx.x, bm = blockIdx.y;
    const int w  = t >> 5, lane = t & 31;
    const int wm = w >> 1, wn = w & 1;      // 4 x 2 warp grid, warp tile 32x64
    const int g  = lane >> 2, tg = lane & 3;

    int rowv[2], kov[2];
#pragma unroll
    for (int j = 0; j < 2; j++) {
        int v = t + 256 * j;
        rowv[j] = v >> 2;
        kov[j]  = (v & 3) * 4;
    }
    const float* PA[2];
    const float* PB[2];
    uint32_t DA[2], DB[2];
#pragma unroll
    for (int j = 0; j < 2; j++) {
        PA[j] = A + (size_t)(bm * 128 + rowv[j]) * KDIM + kov[j];
        PB[j] = B + (size_t)(bn * 128 + rowv[j]) * KDIM + kov[j];
        DA[j] = AsU + (rowv[j] * 24 + kov[j]) * 4;
        DB[j] = BsU + (rowv[j] * 24 + kov[j]) * 4;
    }

    const int NIT = KDIM / 16;

    // prologue: stages 0..2
#pragma unroll
    for (int s = 0; s < 3; s++) {
#pragma unroll
        for (int j = 0; j < 2; j++) {
            cp_async16(DA[j] + s * (GSTRIDE * 4), PA[j] + s * 16);
            cp_async16(DB[j] + s * (GSTRIDE * 4), PB[j] + s * 16);
        }
        cp_commit();
    }

    float acc[2][8][4];
#pragma unroll
    for (int mt = 0; mt < 2; mt++)
#pragma unroll
        for (int nt = 0; nt < 8; nt++)
#pragma unroll
            for (int i = 0; i < 4; i++) acc[mt][nt][i] = 0.f;

    const int ar0 = (wm * 32 + g) * 24 + 2 * tg;       // +mt*384, +192 row+8
    const int br0 = (wn * 64 + g) * 24 + 2 * tg;       // +nt*192

#pragma unroll 1
    for (int it = 0; it < NIT; it++) {
        if (it < NIT - 2)      cp_wait<2>();
        else if (it == NIT - 2) cp_wait<1>();
        else                    cp_wait<0>();
        __syncthreads();

        if (it + 3 < NIT) {
            const int sn = (it + 3) & 3;
#pragma unroll
            for (int j = 0; j < 2; j++) {
                cp_async16(DA[j] + sn * (GSTRIDE * 4), PA[j] + (it + 3) * 16);
                cp_async16(DB[j] + sn * (GSTRIDE * 4), PB[j] + (it + 3) * 16);
            }
            cp_commit();
        }

        const int s = it & 3;
        const float* Ab = As + s * GSTRIDE;
        const float* Bb = Bs + s * GSTRIDE;
#pragma unroll
        for (int kk = 0; kk < 16; kk += 8) {
            float2 af[2][2], bf[8];
#pragma unroll
            for (int mt = 0; mt < 2; mt++) {
                af[mt][0] = *(const float2*)&Ab[ar0 + mt * 384 + kk];
                af[mt][1] = *(const float2*)&Ab[ar0 + mt * 384 + 192 + kk];
            }
#pragma unroll
            for (int nt = 0; nt < 8; nt++)
                bf[nt] = *(const float2*)&Bb[br0 + nt * 192 + kk];
#pragma unroll
            for (int mt = 0; mt < 2; mt++)
#pragma unroll
                for (int nt = 0; nt < 8; nt++)
                    mma_tf32(acc[mt][nt], af[mt][0], af[mt][1], bf[nt]);
        }
    }

#pragma unroll
    for (int mt = 0; mt < 2; mt++) {
        const int m0 = bm * 128 + wm * 32 + mt * 16 + g;
#pragma unroll
        for (int nt = 0; nt < 8; nt++) {
            const int n0 = bn * 128 + wn * 64 + nt * 8 + 2 * tg;
            const float b0 = bias[n0], b1 = bias[n0 + 1];
            float2 r0, r1;
            if (MODE == 0) {
                r0.x = to_tf32(fmaxf(acc[mt][nt][0] + b0, 0.f));
                r0.y = to_tf32(fmaxf(acc[mt][nt][1] + b1, 0.f));
                r1.x = to_tf32(fmaxf(acc[mt][nt][2] + b0, 0.f));
                r1.y = to_tf32(fmaxf(acc[mt][nt][3] + b1, 0.f));
            } else {
                r0.x = 1.f / (1.f + __expf(-(acc[mt][nt][0] + b0)));
                r0.y = 1.f / (1.f + __expf(-(acc[mt][nt][1] + b1)));
                r1.x = 1.f / (1.f + __expf(-(acc[mt][nt][2] + b0)));
                r1.y = 1.f / (1.f + __expf(-(acc[mt][nt][3] + b1)));
            }
            *(float2*)&C[(size_t)m0 * ldc + n0]       = r0;
            *(float2*)&C[(size_t)(m0 + 8) * ldc + n0] = r1;
        }
    }
}

// ============================================================================
extern "C" void kernel_launch(void* const* d_in, const int* in_sizes, int n_in,
                              void* d_out, int out_size)
{
    const float* x   = (const float*)d_in[0];
    const float* w1  = (const float*)d_in[1];
    const float* b1  = (const float*)d_in[2];
    const float* g1  = (const float*)d_in[3];
    const float* be1 = (const float*)d_in[4];
    const float* m1  = (const float*)d_in[5];
    const float* v1  = (const float*)d_in[6];
    const float* w2  = (const float*)d_in[7];
    const float* b2  = (const float*)d_in[8];
    const float* g2  = (const float*)d_in[9];
    const float* be2 = (const float*)d_in[10];
    const float* m2  = (const float*)d_in[11];
    const float* v2  = (const float*)d_in[12];
    const float* wa  = (const float*)d_in[13];
    const float* ba  = (const float*)d_in[14];
    const float* wd1 = (const float*)d_in[15];
    const float* bd1 = (const float*)d_in[16];
    const float* wd2 = (const float*)d_in[17];
    const float* bd2 = (const float*)d_in[18];
    float* out = (float*)d_out;

    const int fused_smem = FU_TOTAL * 4;                    // 225,984 B
    const int gemm_smem  = GSTAGE * GSTRIDE * 2 * 4;        // 98,304 B
    cudaFuncSetAttribute(conv_fused_kernel,
                         cudaFuncAttributeMaxDynamicSharedMemorySize, fused_smem);
    cudaFuncSetAttribute(gemm_tf32_kernel<4096, 0>,
                         cudaFuncAttributeMaxDynamicSharedMemorySize, gemm_smem);
    cudaFuncSetAttribute(gemm_tf32_kernel<512, 1>,
                         cudaFuncAttributeMaxDynamicSharedMemorySize, gemm_smem);

    cvt_wd1_kernel<<<2048, 256>>>(wd1);
    cvt_wd2_kernel<<<64, 256>>>(wd2);
    cvt_w2_kernel<<<72, 256>>>(w2);
    cvt_w1_kernel<<<15, 256>>>(w1);

    conv_fused_kernel<<<148, 256, fused_smem>>>(x, b1, g1, be1, m1, v1,
                                                b2, g2, be2, m2, v2, wa, ba);

    dim3 grid_fc1(4, 64);
    gemm_tf32_kernel<4096, 0><<<grid_fc1, 256, gemm_smem>>>(bd1, out);
    dim3 grid_fc2(1, 64);
    gemm_tf32_kernel<512, 1><<<grid_fc2, 256, gemm_smem>>>(bd2, out);
}